// round 12
// baseline (speedup 1.0000x reference)
#include <cuda_runtime.h>
#include <cuda_fp16.h>
#include <math.h>
#include <cstdint>

// Problem constants
#define T_SEQ   2048
#define C_EMB   2048
#define N_HEADS 16
#define N_KVH   4
#define HEAD_D  128
#define KV_W    (N_KVH * HEAD_D)   // 512
#define QKV_W   (C_EMB + 2 * KV_W) // 3072

// -------- scratch (device globals; no allocation allowed) --------
__device__ float  g_qkv[T_SEQ * QKV_W];
__device__ __half g_qh[T_SEQ * C_EMB];
__device__ __half g_kh[N_KVH * T_SEQ * HEAD_D];
__device__ __half g_vh[N_KVH * T_SEQ * HEAD_D];
__device__ __half g_yh[T_SEQ * C_EMB];
__device__ __half g_xh[T_SEQ * C_EMB];
__device__ __half g_wqkvt[QKV_W * C_EMB];
__device__ __half g_wot[C_EMB * C_EMB];
__device__ float  g_bqkv[QKV_W];

// =====================================================================
// helpers
// =====================================================================
__device__ __forceinline__ uint32_t smem_u32(const void* p) {
    uint32_t a;
    asm("{ .reg .u64 t; cvta.to.shared.u64 t, %1; cvt.u32.u64 %0, t; }" : "=r"(a) : "l"(p));
    return a;
}
__device__ __forceinline__ void cp_async16(uint32_t dst, const void* src) {
    asm volatile("cp.async.ca.shared.global [%0], [%1], 16;" :: "r"(dst), "l"(src) : "memory");
}
__device__ __forceinline__ void cp_commit() {
    asm volatile("cp.async.commit_group;" ::: "memory");
}
template <int N>
__device__ __forceinline__ void cp_wait() {
    asm volatile("cp.async.wait_group %0;" :: "n"(N) : "memory");
}
__device__ __forceinline__ void ldm_x4(unsigned* r, uint32_t addr) {
    asm volatile("ldmatrix.sync.aligned.m8n8.x4.shared.b16 {%0,%1,%2,%3}, [%4];"
        : "=r"(r[0]), "=r"(r[1]), "=r"(r[2]), "=r"(r[3]) : "r"(addr));
}
__device__ __forceinline__ void ldm_x4t(unsigned* r, uint32_t addr) {
    asm volatile("ldmatrix.sync.aligned.m8n8.x4.trans.shared.b16 {%0,%1,%2,%3}, [%4];"
        : "=r"(r[0]), "=r"(r[1]), "=r"(r[2]), "=r"(r[3]) : "r"(addr));
}
__device__ __forceinline__ void mma_f16(float* c, const unsigned* a, const unsigned* b) {
    asm volatile(
        "mma.sync.aligned.m16n8k16.row.col.f32.f16.f16.f32 "
        "{%0,%1,%2,%3}, {%4,%5,%6,%7}, {%8,%9}, {%0,%1,%2,%3};"
        : "+f"(c[0]), "+f"(c[1]), "+f"(c[2]), "+f"(c[3])
        : "r"(a[0]), "r"(a[1]), "r"(a[2]), "r"(a[3]), "r"(b[0]), "r"(b[1]));
}
__device__ __forceinline__ unsigned pack_h2(float a, float b) {
    __half2 h = __floats2half2_rn(a, b);
    return *reinterpret_cast<unsigned*>(&h);
}

// =====================================================================
// fp16 mma GEMM — CTA 128(M) x 256(N), 16 warps of 32x64, 512 threads.
// 4 slots of BK=32, 2 k-tiles per sync/wait. 4 warps/SMSP for latency
// hiding (R11 profile: occ 12.4%, issue 13.4% -> latency-bound).
// =====================================================================
#define GROWB     80                          // 64B data + 16B pad per row
#define G_ASZ     (128 * GROWB)               // 10240
#define G_BSZ     (256 * GROWB)               // 20480
#define SLOT_SZ   (G_ASZ + G_BSZ)             // 30720
#define GSMEM     (4 * SLOT_SZ)               // 122880

__global__ __launch_bounds__(512, 1)
void gemm_h(const __half* __restrict__ A, const __half* __restrict__ Bt,
            const float* __restrict__ bias, float* __restrict__ C,
            int M, int N, int K)
{
    extern __shared__ char smem[];
    const uint32_t sbase = smem_u32(smem);

    const int tid  = threadIdx.x;
    const int warp = tid >> 5;
    const int lane = tid & 31;
    const int g    = lane >> 2;
    const int tg   = lane & 3;
    const int wm   = warp >> 2;     // 0..3  (32-row band)
    const int wn   = warp & 3;      // 0..3  (64-col band)
    const int m0   = blockIdx.y * 128;
    const int n0   = blockIdx.x * 256;

    const int lr8  = lane & 7;
    const int rsel = (lane >> 3) & 1;
    const int ksel = (lane >> 4) & 1;
    const uint32_t a_base = sbase +
        (uint32_t)((wm * 32 + lr8 + rsel * 8) * GROWB + ksel * 16);
    const uint32_t b_base = sbase + G_ASZ +
        (uint32_t)((wn * 64 + lr8 + ksel * 8) * GROWB + rsel * 16);

    float acc[2][8][4];
#pragma unroll
    for (int mt = 0; mt < 2; mt++)
#pragma unroll
        for (int nt = 0; nt < 8; nt++)
#pragma unroll
            for (int r = 0; r < 4; r++) acc[mt][nt][r] = 0.f;

    const int NS = K / 64;

    // loader: A = 512 16B chunks (1/thread), B = 1024 chunks (2/thread)
#define LOAD_TILE(kt)                                                          \
    do {                                                                       \
        const uint32_t so = (uint32_t)(((kt) & 3) * SLOT_SZ);                  \
        const __half* Ak = A + (size_t)m0 * K + (size_t)(kt) * 32;             \
        const __half* Bk = Bt + (size_t)n0 * K + (size_t)(kt) * 32;            \
        {                                                                      \
            int row = tid >> 2, c = tid & 3;                                   \
            cp_async16(sbase + so + (uint32_t)(row * GROWB + c * 16),          \
                       Ak + (size_t)row * K + c * 8);                          \
        }                                                                      \
        _Pragma("unroll")                                                      \
        for (int it = 0; it < 2; it++) {                                       \
            int idx = tid + it * 512;                                          \
            int row = idx >> 2, c = idx & 3;                                   \
            cp_async16(sbase + so + G_ASZ + (uint32_t)(row * GROWB + c * 16),  \
                       Bk + (size_t)row * K + c * 8);                          \
        }                                                                      \
    } while (0)

    LOAD_TILE(0);
    LOAD_TILE(1);
    cp_commit();

    for (int s = 0; s < NS; s++) {
        __syncthreads();
        if (s + 1 < NS) {
            LOAD_TILE(2 * s + 2);
            LOAD_TILE(2 * s + 3);
            cp_commit();
            cp_wait<1>();
        } else {
            cp_wait<0>();
        }
        __syncthreads();

#pragma unroll
        for (int q = 0; q < 2; q++) {
            const uint32_t soff = (uint32_t)(((2 * s + q) & 3) * SLOT_SZ);
#pragma unroll
            for (int ks = 0; ks < 2; ks++) {
                unsigned af[2][4], bf[4][4];
#pragma unroll
                for (int mt = 0; mt < 2; mt++)
                    ldm_x4(af[mt], a_base + soff + (uint32_t)(mt * 16 * GROWB + ks * 32));
#pragma unroll
                for (int pr = 0; pr < 4; pr++)
                    ldm_x4(bf[pr], b_base + soff + (uint32_t)(pr * 16 * GROWB + ks * 32));
#pragma unroll
                for (int mt = 0; mt < 2; mt++)
#pragma unroll
                    for (int nt = 0; nt < 8; nt++)
                        mma_f16(acc[mt][nt], af[mt], &bf[nt >> 1][(nt & 1) * 2]);
            }
        }
    }
#undef LOAD_TILE

    // epilogue
#pragma unroll
    for (int mt = 0; mt < 2; mt++) {
        int r0 = m0 + wm * 32 + mt * 16 + g;
#pragma unroll
        for (int nt = 0; nt < 8; nt++) {
            int c = n0 + wn * 64 + nt * 8 + 2 * tg;
            float bx = 0.f, by = 0.f;
            if (bias) { bx = bias[c]; by = bias[c + 1]; }
            float2 v0 = make_float2(acc[mt][nt][0] + bx, acc[mt][nt][1] + by);
            float2 v1 = make_float2(acc[mt][nt][2] + bx, acc[mt][nt][3] + by);
            *(float2*)&C[(size_t)r0 * N + c]       = v0;
            *(float2*)&C[(size_t)(r0 + 8) * N + c] = v1;
        }
    }
}

// =====================================================================
// x -> half
// =====================================================================
__global__ __launch_bounds__(256)
void convx_kernel(const float* __restrict__ x)
{
    int i = (blockIdx.x * 256 + threadIdx.x) * 4;
    float4 v = *(const float4*)&x[i];
    *(__half2*)&g_xh[i]     = __floats2half2_rn(v.x, v.y);
    *(__half2*)&g_xh[i + 2] = __floats2half2_rn(v.z, v.w);
}

// =====================================================================
// weight transposes and bias concat
// =====================================================================
__global__ __launch_bounds__(256)
void transpose_w(const float* __restrict__ Wq, const float* __restrict__ Wk,
                 const float* __restrict__ Wv, const float* __restrict__ Wo)
{
    __shared__ float tile[32][33];
    const int z = blockIdx.z;
    const float* in;
    __half* out;
    int C;
    if (z == 0)      { in = Wq; out = g_wqkvt;               C = C_EMB; }
    else if (z == 1) { in = Wk; out = g_wqkvt + 2048 * 2048; C = KV_W; }
    else if (z == 2) { in = Wv; out = g_wqkvt + 2560 * 2048; C = KV_W; }
    else             { in = Wo; out = g_wot;                 C = C_EMB; }
    const int bx = blockIdx.x * 32;
    if (bx >= C) return;
    const int by = blockIdx.y * 32;
    const int R = C_EMB;
    const int x = bx + threadIdx.x;
#pragma unroll
    for (int i = threadIdx.y; i < 32; i += 8)
        tile[i][threadIdx.x] = in[(size_t)(by + i) * C + x];
    __syncthreads();
    const int ox = by + threadIdx.x;
#pragma unroll
    for (int i = threadIdx.y; i < 32; i += 8)
        out[(size_t)(bx + i) * R + ox] = __float2half(tile[threadIdx.x][i]);
}

__global__ __launch_bounds__(256)
void bias_concat(const float* __restrict__ bq, const float* __restrict__ bk,
                 const float* __restrict__ bv)
{
    int idx = blockIdx.x * 256 + threadIdx.x;
    if (idx >= QKV_W) return;
    float v = (idx < 2048) ? bq[idx]
            : (idx < 2560) ? bk[idx - 2048]
                           : bv[idx - 2560];
    g_bqkv[idx] = v;
}

// =====================================================================
// RoPE + V copy (validated R9)
// =====================================================================
__device__ __forceinline__ int sec3(int d) {
    if (d < 16)  return 0;
    if (d < 40)  return 1;
    if (d < 64)  return 2;
    if (d < 80)  return 0;
    if (d < 104) return 1;
    return 2;
}

__global__ __launch_bounds__(256)
void rope2_kernel(const float* __restrict__ cosb, const float* __restrict__ sinb,
                  float* __restrict__ out_k, float* __restrict__ out_v)
{
    __shared__ float cs[384], sn[384];
    const int t   = blockIdx.x;
    const int tid = threadIdx.x;

    for (int i = tid; i < 384; i += 256) {
        int ch = i >> 7, d = i & 127;
        cs[i] = cosb[(size_t)ch * T_SEQ * HEAD_D + (size_t)t * HEAD_D + d];
        sn[i] = sinb[(size_t)ch * T_SEQ * HEAD_D + (size_t)t * HEAD_D + d];
    }
    __syncthreads();

    const float* row = g_qkv + (size_t)t * QKV_W;

#pragma unroll
    for (int it = 0; it < 5; it++) {
        int p  = it * 256 + tid;
        int hh = p >> 6;
        int d  = p & 63;
        int d2 = d + 64;
        float c1 = cs[sec3(d)  * 128 + d],  s1 = sn[sec3(d)  * 128 + d];
        float c2 = cs[sec3(d2) * 128 + d2], s2 = sn[sec3(d2) * 128 + d2];

        const float* base = row + ((hh < N_HEADS) ? hh * HEAD_D
                                                  : C_EMB + (hh - N_HEADS) * HEAD_D);
        float x1 = base[d], x2 = base[d2];
        float r1 = x1 * c1 - x2 * s1;
        float r2 = x2 * c2 + x1 * s2;

        if (hh < N_HEADS) {
            g_qh[(size_t)t * C_EMB + hh * HEAD_D + d]  = __float2half(r1);
            g_qh[(size_t)t * C_EMB + hh * HEAD_D + d2] = __float2half(r2);
        } else {
            int h = hh - N_HEADS;
            size_t o = (size_t)h * T_SEQ * HEAD_D + (size_t)t * HEAD_D;
            out_k[o + d]  = r1;
            out_k[o + d2] = r2;
            g_kh[o + d]   = __float2half(r1);
            g_kh[o + d2]  = __float2half(r2);
        }
    }

#pragma unroll
    for (int it = 0; it < 2; it++) {
        int idx = it * 256 + tid;
        int h = idx >> 7, d = idx & 127;
        float v = row[C_EMB + KV_W + idx];
        size_t o = (size_t)h * T_SEQ * HEAD_D + (size_t)t * HEAD_D + d;
        out_v[o] = v;
        g_vh[o]  = __float2half(v);
    }
}

// =====================================================================
// fp16 mma flash attention (validated R9)
// =====================================================================
#define AROWB   272
#define AQ_SZ   (128 * AROWB)
#define AKV_SZ  (32 * AROWB)
#define ATSMEM  (AQ_SZ + 4 * AKV_SZ)

__global__ __launch_bounds__(256, 2)
void attn_mma(__half* __restrict__ Y)
{
    extern __shared__ char sm[];
    const uint32_t qs  = smem_u32(sm);
    const uint32_t ks0 = qs + AQ_SZ;
    const uint32_t vs0 = ks0 + 2 * AKV_SZ;

    const int h    = blockIdx.y;
    const int kvh  = h >> 2;
    const int q0   = blockIdx.x * 128;
    const int tid  = threadIdx.x;
    const int warp = tid >> 5;
    const int lane = tid & 31;
    const int g    = lane >> 2;
    const int tg   = lane & 3;
    const int lr8  = lane & 7;
    const int rsel = (lane >> 3) & 1;
    const int ksel = (lane >> 4) & 1;
    const float scale = 0.08838834764831845f;

    const __half* Ksrc = g_kh + (size_t)kvh * T_SEQ * HEAD_D;
    const __half* Vsrc = g_vh + (size_t)kvh * T_SEQ * HEAD_D;

    {
        const __half* Qsrc = g_qh + (size_t)q0 * C_EMB + h * HEAD_D;
        for (int i = tid; i < 128 * 16; i += 256) {
            int row = i >> 4, c = i & 15;
            cp_async16(qs + (uint32_t)(row * AROWB + c * 16),
                       Qsrc + (size_t)row * C_EMB + c * 8);
        }
        cp_commit();
    }

    const int ntiles = q0 / 32 + 4;

    for (int i = tid; i < 32 * 16; i += 256) {
        int row = i >> 4, c = i & 15;
        cp_async16(ks0 + (uint32_t)(row * AROWB + c * 16),
                   Ksrc + (size_t)row * HEAD_D + c * 8);
        cp_async16(vs0 + (uint32_t)(row * AROWB + c * 16),
                   Vsrc + (size_t)row * HEAD_D + c * 8);
    }
    cp_commit();

    const uint32_t qa = qs + (uint32_t)((warp * 16 + lr8 + rsel * 8) * AROWB + ksel * 16);

    float O[16][4];
#pragma unroll
    for (int n = 0; n < 16; n++)
#pragma unroll
        for (int r = 0; r < 4; r++) O[n][r] = 0.f;
    float m0 = -1e30f, m1 = -1e30f, l0 = 0.f, l1 = 0.f;

    const int row0  = q0 + warp * 16 + g;
    const int wlast = q0 + warp * 16 + 15;

    for (int kt = 0; kt < ntiles; kt++) {
        if (kt + 1 < ntiles) {
            const uint32_t kb = ks0 + (uint32_t)(((kt + 1) & 1) * AKV_SZ);
            const uint32_t vb = vs0 + (uint32_t)(((kt + 1) & 1) * AKV_SZ);
            const __half* Ki = Ksrc + (size_t)(kt + 1) * 32 * HEAD_D;
            const __half* Vi = Vsrc + (size_t)(kt + 1) * 32 * HEAD_D;
            for (int i = tid; i < 32 * 16; i += 256) {
                int row = i >> 4, c = i & 15;
                cp_async16(kb + (uint32_t)(row * AROWB + c * 16),
                           Ki + (size_t)row * HEAD_D + c * 8);
                cp_async16(vb + (uint32_t)(row * AROWB + c * 16),
                           Vi + (size_t)row * HEAD_D + c * 8);
            }
            cp_commit();
            cp_wait<1>();
        } else {
            cp_wait<0>();
        }
        __syncthreads();

        const int kk0 = kt * 32;
        const uint32_t kbuf = ks0 + (uint32_t)((kt & 1) * AKV_SZ);
        const uint32_t vbuf = vs0 + (uint32_t)((kt & 1) * AKV_SZ);

        if (kk0 <= wlast) {
            const uint32_t ka = kbuf + (uint32_t)((lr8 + ksel * 8) * AROWB + rsel * 16);

            float S[4][4];
#pragma unroll
            for (int nt = 0; nt < 4; nt++)
#pragma unroll
                for (int r = 0; r < 4; r++) S[nt][r] = 0.f;

#pragma unroll
            for (int kc = 0; kc < 8; kc++) {
                unsigned aq[4], bk2[2][4];
                ldm_x4(aq, qa + (uint32_t)(kc * 32));
                ldm_x4(bk2[0], ka + (uint32_t)(kc * 32));
                ldm_x4(bk2[1], ka + (uint32_t)(16 * AROWB + kc * 32));
#pragma unroll
                for (int nt = 0; nt < 4; nt++)
                    mma_f16(S[nt], aq, &bk2[nt >> 1][(nt & 1) * 2]);
            }

            float rm0 = -1e30f, rm1 = -1e30f;
#pragma unroll
            for (int nt = 0; nt < 4; nt++) {
                int cb = kk0 + nt * 8 + 2 * tg;
                S[nt][0] = (cb     <= row0)     ? S[nt][0] * scale : -1e30f;
                S[nt][1] = (cb + 1 <= row0)     ? S[nt][1] * scale : -1e30f;
                S[nt][2] = (cb     <= row0 + 8) ? S[nt][2] * scale : -1e30f;
                S[nt][3] = (cb + 1 <= row0 + 8) ? S[nt][3] * scale : -1e30f;
                rm0 = fmaxf(rm0, fmaxf(S[nt][0], S[nt][1]));
                rm1 = fmaxf(rm1, fmaxf(S[nt][2], S[nt][3]));
            }
            rm0 = fmaxf(rm0, __shfl_xor_sync(0xffffffffu, rm0, 1));
            rm0 = fmaxf(rm0, __shfl_xor_sync(0xffffffffu, rm0, 2));
            rm1 = fmaxf(rm1, __shfl_xor_sync(0xffffffffu, rm1, 1));
            rm1 = fmaxf(rm1, __shfl_xor_sync(0xffffffffu, rm1, 2));

            float mn0 = fmaxf(m0, rm0), mn1 = fmaxf(m1, rm1);
            float c0 = __expf(m0 - mn0), c1 = __expf(m1 - mn1);
            float s0 = 0.f, s1 = 0.f;
#pragma unroll
            for (int nt = 0; nt < 4; nt++) {
                S[nt][0] = __expf(S[nt][0] - mn0);
                S[nt][1] = __expf(S[nt][1] - mn0);
                S[nt][2] = __expf(S[nt][2] - mn1);
                S[nt][3] = __expf(S[nt][3] - mn1);
                s0 += S[nt][0] + S[nt][1];
                s1 += S[nt][2] + S[nt][3];
            }
            s0 += __shfl_xor_sync(0xffffffffu, s0, 1);
            s0 += __shfl_xor_sync(0xffffffffu, s0, 2);
            s1 += __shfl_xor_sync(0xffffffffu, s1, 1);
            s1 += __shfl_xor_sync(0xffffffffu, s1, 2);
            l0 = l0 * c0 + s0;
            l1 = l1 * c1 + s1;
            m0 = mn0; m1 = mn1;
#pragma unroll
            for (int n = 0; n < 16; n++) {
                O[n][0] *= c0; O[n][1] *= c0;
                O[n][2] *= c1; O[n][3] *= c1;
            }

#pragma unroll
            for (int kc = 0; kc < 2; kc++) {
                unsigned pa[4];
                pa[0] = pack_h2(S[2 * kc][0],     S[2 * kc][1]);
                pa[1] = pack_h2(S[2 * kc][2],     S[2 * kc][3]);
                pa[2] = pack_h2(S[2 * kc + 1][0], S[2 * kc + 1][1]);
                pa[3] = pack_h2(S[2 * kc + 1][2], S[2 * kc + 1][3]);
                const uint32_t va = vbuf +
                    (uint32_t)((kc * 16 + lr8 + rsel * 8) * AROWB + ksel * 16);
#pragma unroll
                for (int dc = 0; dc < 8; dc++) {
                    unsigned vb[4];
                    ldm_x4t(vb, va + (uint32_t)(dc * 32));
                    mma_f16(O[dc * 2],     pa, &vb[0]);
                    mma_f16(O[dc * 2 + 1], pa, &vb[2]);
                }
            }
        }
        __syncthreads();
    }

    float inv0 = 1.f / l0, inv1 = 1.f / l1;
#pragma unroll
    for (int n = 0; n < 16; n++) {
        int c = h * HEAD_D + n * 8 + 2 * tg;
        __half2 h0 = __floats2half2_rn(O[n][0] * inv0, O[n][1] * inv0);
        __half2 h1 = __floats2half2_rn(O[n][2] * inv1, O[n][3] * inv1);
        *(__half2*)&Y[(size_t)row0 * C_EMB + c]       = h0;
        *(__half2*)&Y[(size_t)(row0 + 8) * C_EMB + c] = h1;
    }
}

// =====================================================================
// launch
// =====================================================================
extern "C" void kernel_launch(void* const* d_in, const int* in_sizes, int n_in,
                              void* d_out, int out_size)
{
    (void)in_sizes; (void)n_in; (void)out_size;
    const float* x    = (const float*)d_in[0];
    const float* cosb = (const float*)d_in[1];
    const float* sinb = (const float*)d_in[2];
    const float* Wq   = (const float*)d_in[3];
    const float* bq   = (const float*)d_in[4];
    const float* Wk   = (const float*)d_in[5];
    const float* bk   = (const float*)d_in[6];
    const float* Wv   = (const float*)d_in[7];
    const float* bv   = (const float*)d_in[8];
    const float* Wo   = (const float*)d_in[9];

    float* out   = (float*)d_out;
    float* out_y = out;
    float* out_k = out + (size_t)T_SEQ * C_EMB;
    float* out_v = out_k + (size_t)N_KVH * T_SEQ * HEAD_D;

    float*  qkvb; cudaGetSymbolAddress((void**)&qkvb, g_qkv);
    __half* yhb;  cudaGetSymbolAddress((void**)&yhb,  g_yh);
    __half* xhb;  cudaGetSymbolAddress((void**)&xhb,  g_xh);
    __half* wqkv; cudaGetSymbolAddress((void**)&wqkv, g_wqkvt);
    __half* wot;  cudaGetSymbolAddress((void**)&wot,  g_wot);
    float*  bqkv; cudaGetSymbolAddress((void**)&bqkv, g_bqkv);

    cudaFuncSetAttribute(gemm_h, cudaFuncAttributeMaxDynamicSharedMemorySize, GSMEM);
    cudaFuncSetAttribute(attn_mma, cudaFuncAttributeMaxDynamicSharedMemorySize, ATSMEM);

    // 1: weight transposes
    transpose_w<<<dim3(64, 64, 4), dim3(32, 8)>>>(Wq, Wk, Wv, Wo);

    // 2: bias concat
    bias_concat<<<(QKV_W + 255) / 256, 256>>>(bq, bk, bv);

    // 3: x -> half
    convx_kernel<<<(T_SEQ * C_EMB / 4) / 256, 256>>>(x);

    // 4: fused QKV projection  <-- ncu-captured launch
    gemm_h<<<dim3(QKV_W / 256, T_SEQ / 128), 512, GSMEM>>>(xhb, wqkv, bqkv, qkvb, T_SEQ, QKV_W, C_EMB);

    // 5: RoPE + V copy
    rope2_kernel<<<T_SEQ, 256>>>(cosb, sinb, out_k, out_v);

    // 6: flash attention
    attn_mma<<<dim3(T_SEQ / 128, N_HEADS), 256, ATSMEM>>>(yhb);

    // 7: output projection
    gemm_h<<<dim3(C_EMB / 256, T_SEQ / 128), 512, GSMEM>>>(yhb, wot, nullptr, out_y, T_SEQ, C_EMB, C_EMB);
}

// round 13
// speedup vs baseline: 1.0306x; 1.0306x over previous
#include <cuda_runtime.h>
#include <cuda_fp16.h>
#include <math.h>
#include <cstdint>

// Problem constants
#define T_SEQ   2048
#define C_EMB   2048
#define N_HEADS 16
#define N_KVH   4
#define HEAD_D  128
#define KV_W    (N_KVH * HEAD_D)   // 512
#define QKV_W   (C_EMB + 2 * KV_W) // 3072

// -------- scratch (device globals; no allocation allowed) --------
__device__ float  g_qkv[T_SEQ * QKV_W];
__device__ __half g_qh[T_SEQ * C_EMB];
__device__ __half g_kh[N_KVH * T_SEQ * HEAD_D];
__device__ __half g_vh[N_KVH * T_SEQ * HEAD_D];
__device__ __half g_yh[T_SEQ * C_EMB];
__device__ __half g_xh[T_SEQ * C_EMB];
__device__ __half g_wqkvt[QKV_W * C_EMB];
__device__ __half g_wot[C_EMB * C_EMB];
__device__ float  g_bqkv[QKV_W];

// =====================================================================
// helpers
// =====================================================================
__device__ __forceinline__ uint32_t smem_u32(const void* p) {
    uint32_t a;
    asm("{ .reg .u64 t; cvta.to.shared.u64 t, %1; cvt.u32.u64 %0, t; }" : "=r"(a) : "l"(p));
    return a;
}
__device__ __forceinline__ void cp_async16(uint32_t dst, const void* src) {
    asm volatile("cp.async.ca.shared.global [%0], [%1], 16;" :: "r"(dst), "l"(src) : "memory");
}
__device__ __forceinline__ void cp_commit() {
    asm volatile("cp.async.commit_group;" ::: "memory");
}
template <int N>
__device__ __forceinline__ void cp_wait() {
    asm volatile("cp.async.wait_group %0;" :: "n"(N) : "memory");
}
__device__ __forceinline__ void ldm_x4(unsigned* r, uint32_t addr) {
    asm volatile("ldmatrix.sync.aligned.m8n8.x4.shared.b16 {%0,%1,%2,%3}, [%4];"
        : "=r"(r[0]), "=r"(r[1]), "=r"(r[2]), "=r"(r[3]) : "r"(addr));
}
__device__ __forceinline__ void ldm_x4t(unsigned* r, uint32_t addr) {
    asm volatile("ldmatrix.sync.aligned.m8n8.x4.trans.shared.b16 {%0,%1,%2,%3}, [%4];"
        : "=r"(r[0]), "=r"(r[1]), "=r"(r[2]), "=r"(r[3]) : "r"(addr));
}
__device__ __forceinline__ void mma_f16(float* c, const unsigned* a, const unsigned* b) {
    asm volatile(
        "mma.sync.aligned.m16n8k16.row.col.f32.f16.f16.f32 "
        "{%0,%1,%2,%3}, {%4,%5,%6,%7}, {%8,%9}, {%0,%1,%2,%3};"
        : "+f"(c[0]), "+f"(c[1]), "+f"(c[2]), "+f"(c[3])
        : "r"(a[0]), "r"(a[1]), "r"(a[2]), "r"(a[3]), "r"(b[0]), "r"(b[1]));
}
__device__ __forceinline__ unsigned pack_h2(float a, float b) {
    __half2 h = __floats2half2_rn(a, b);
    return *reinterpret_cast<unsigned*>(&h);
}

// =====================================================================
// fp16 mma GEMM — CTA 128(M) x 256(N), 8 warps of 64x64, 256 threads.
// 6 slots of BK=32; 2 k-tiles per group; 3 groups in flight
// (issue-after-compute, wait<2>): ~2 group-compute times of latency
// cover for the cp.async arrivals (R12 post-mortem: arrival-latency
// bound, not warp-count bound).
// =====================================================================
#define GROWB     80                          // 64B data + 16B pad per row
#define G_ASZ     (128 * GROWB)               // 10240
#define G_BSZ     (256 * GROWB)               // 20480
#define SLOT_SZ   (G_ASZ + G_BSZ)             // 30720
#define NSLOTS    6
#define GSMEM     (NSLOTS * SLOT_SZ)          // 184320

__global__ __launch_bounds__(256, 1)
void gemm_h(const __half* __restrict__ A, const __half* __restrict__ Bt,
            const float* __restrict__ bias, float* __restrict__ C,
            int M, int N, int K)
{
    extern __shared__ char smem[];
    const uint32_t sbase = smem_u32(smem);

    const int tid  = threadIdx.x;
    const int warp = tid >> 5;
    const int lane = tid & 31;
    const int g    = lane >> 2;
    const int tg   = lane & 3;
    const int wm   = warp >> 2;     // 0..1  (64-row band)
    const int wn   = warp & 3;      // 0..3  (64-col band)
    const int m0   = blockIdx.y * 128;
    const int n0   = blockIdx.x * 256;

    const int lr8  = lane & 7;
    const int rsel = (lane >> 3) & 1;
    const int ksel = (lane >> 4) & 1;
    const uint32_t a_base = sbase +
        (uint32_t)((wm * 64 + lr8 + rsel * 8) * GROWB + ksel * 16);
    const uint32_t b_base = sbase + G_ASZ +
        (uint32_t)((wn * 64 + lr8 + ksel * 8) * GROWB + rsel * 16);

    float acc[4][8][4];
#pragma unroll
    for (int mt = 0; mt < 4; mt++)
#pragma unroll
        for (int nt = 0; nt < 8; nt++)
#pragma unroll
            for (int r = 0; r < 4; r++) acc[mt][nt][r] = 0.f;

    const int NG = K / 64;           // groups of 2 k-tiles (NG >= 3)

    // loader: per k-tile, A = 512 16B chunks (2/thread), B = 1024 (4/thread)
#define LOAD_TILE(kt)                                                          \
    do {                                                                       \
        const uint32_t so = (uint32_t)(((kt) % NSLOTS) * SLOT_SZ);             \
        const __half* Ak = A + (size_t)m0 * K + (size_t)(kt) * 32;             \
        const __half* Bk = Bt + (size_t)n0 * K + (size_t)(kt) * 32;            \
        _Pragma("unroll")                                                      \
        for (int it = 0; it < 2; it++) {                                       \
            int idx = tid + it * 256;                                          \
            int row = idx >> 2, c = idx & 3;                                   \
            cp_async16(sbase + so + (uint32_t)(row * GROWB + c * 16),          \
                       Ak + (size_t)row * K + c * 8);                          \
        }                                                                      \
        _Pragma("unroll")                                                      \
        for (int it = 0; it < 4; it++) {                                       \
            int idx = tid + it * 256;                                          \
            int row = idx >> 2, c = idx & 3;                                   \
            cp_async16(sbase + so + G_ASZ + (uint32_t)(row * GROWB + c * 16),  \
                       Bk + (size_t)row * K + c * 8);                          \
        }                                                                      \
    } while (0)

    // prologue: groups 0,1,2 (k-tiles 0..5)
#pragma unroll
    for (int gp = 0; gp < 3; gp++) {
        LOAD_TILE(2 * gp);
        LOAD_TILE(2 * gp + 1);
        cp_commit();
    }

    for (int s = 0; s < NG; s++) {
        cp_wait<2>();        // group s arrived (2 newer groups may be in flight)
        __syncthreads();     // cross-thread visibility of async-copied data

        // compute group s: k-tiles 2s, 2s+1
#pragma unroll
        for (int q = 0; q < 2; q++) {
            const uint32_t soff = (uint32_t)(((2 * s + q) % NSLOTS) * SLOT_SZ);
#pragma unroll
            for (int ks = 0; ks < 2; ks++) {
                unsigned af[4][4], bf[4][4];
#pragma unroll
                for (int mt = 0; mt < 4; mt++)
                    ldm_x4(af[mt], a_base + soff + (uint32_t)(mt * 16 * GROWB + ks * 32));
#pragma unroll
                for (int pr = 0; pr < 4; pr++)
                    ldm_x4(bf[pr], b_base + soff + (uint32_t)(pr * 16 * GROWB + ks * 32));
#pragma unroll
                for (int mt = 0; mt < 4; mt++)
#pragma unroll
                    for (int nt = 0; nt < 8; nt++)
                        mma_f16(acc[mt][nt], af[mt], &bf[nt >> 1][(nt & 1) * 2]);
            }
        }

        __syncthreads();     // all warps done reading group s's slots

        // issue group s+3 (reuses group s's slots); always commit
        if (s + 3 < NG) {
            LOAD_TILE(2 * (s + 3));
            LOAD_TILE(2 * (s + 3) + 1);
        }
        cp_commit();
    }
#undef LOAD_TILE

    // epilogue
#pragma unroll
    for (int mt = 0; mt < 4; mt++) {
        int r0 = m0 + wm * 64 + mt * 16 + g;
#pragma unroll
        for (int nt = 0; nt < 8; nt++) {
            int c = n0 + wn * 64 + nt * 8 + 2 * tg;
            float bx = 0.f, by = 0.f;
            if (bias) { bx = bias[c]; by = bias[c + 1]; }
            float2 v0 = make_float2(acc[mt][nt][0] + bx, acc[mt][nt][1] + by);
            float2 v1 = make_float2(acc[mt][nt][2] + bx, acc[mt][nt][3] + by);
            *(float2*)&C[(size_t)r0 * N + c]       = v0;
            *(float2*)&C[(size_t)(r0 + 8) * N + c] = v1;
        }
    }
}

// =====================================================================
// x -> half
// =====================================================================
__global__ __launch_bounds__(256)
void convx_kernel(const float* __restrict__ x)
{
    int i = (blockIdx.x * 256 + threadIdx.x) * 4;
    float4 v = *(const float4*)&x[i];
    *(__half2*)&g_xh[i]     = __floats2half2_rn(v.x, v.y);
    *(__half2*)&g_xh[i + 2] = __floats2half2_rn(v.z, v.w);
}

// =====================================================================
// weight transposes and bias concat
// =====================================================================
__global__ __launch_bounds__(256)
void transpose_w(const float* __restrict__ Wq, const float* __restrict__ Wk,
                 const float* __restrict__ Wv, const float* __restrict__ Wo)
{
    __shared__ float tile[32][33];
    const int z = blockIdx.z;
    const float* in;
    __half* out;
    int C;
    if (z == 0)      { in = Wq; out = g_wqkvt;               C = C_EMB; }
    else if (z == 1) { in = Wk; out = g_wqkvt + 2048 * 2048; C = KV_W; }
    else if (z == 2) { in = Wv; out = g_wqkvt + 2560 * 2048; C = KV_W; }
    else             { in = Wo; out = g_wot;                 C = C_EMB; }
    const int bx = blockIdx.x * 32;
    if (bx >= C) return;
    const int by = blockIdx.y * 32;
    const int R = C_EMB;
    const int x = bx + threadIdx.x;
#pragma unroll
    for (int i = threadIdx.y; i < 32; i += 8)
        tile[i][threadIdx.x] = in[(size_t)(by + i) * C + x];
    __syncthreads();
    const int ox = by + threadIdx.x;
#pragma unroll
    for (int i = threadIdx.y; i < 32; i += 8)
        out[(size_t)(bx + i) * R + ox] = __float2half(tile[threadIdx.x][i]);
}

__global__ __launch_bounds__(256)
void bias_concat(const float* __restrict__ bq, const float* __restrict__ bk,
                 const float* __restrict__ bv)
{
    int idx = blockIdx.x * 256 + threadIdx.x;
    if (idx >= QKV_W) return;
    float v = (idx < 2048) ? bq[idx]
            : (idx < 2560) ? bk[idx - 2048]
                           : bv[idx - 2560];
    g_bqkv[idx] = v;
}

// =====================================================================
// RoPE + V copy (validated R9)
// =====================================================================
__device__ __forceinline__ int sec3(int d) {
    if (d < 16)  return 0;
    if (d < 40)  return 1;
    if (d < 64)  return 2;
    if (d < 80)  return 0;
    if (d < 104) return 1;
    return 2;
}

__global__ __launch_bounds__(256)
void rope2_kernel(const float* __restrict__ cosb, const float* __restrict__ sinb,
                  float* __restrict__ out_k, float* __restrict__ out_v)
{
    __shared__ float cs[384], sn[384];
    const int t   = blockIdx.x;
    const int tid = threadIdx.x;

    for (int i = tid; i < 384; i += 256) {
        int ch = i >> 7, d = i & 127;
        cs[i] = cosb[(size_t)ch * T_SEQ * HEAD_D + (size_t)t * HEAD_D + d];
        sn[i] = sinb[(size_t)ch * T_SEQ * HEAD_D + (size_t)t * HEAD_D + d];
    }
    __syncthreads();

    const float* row = g_qkv + (size_t)t * QKV_W;

#pragma unroll
    for (int it = 0; it < 5; it++) {
        int p  = it * 256 + tid;
        int hh = p >> 6;
        int d  = p & 63;
        int d2 = d + 64;
        float c1 = cs[sec3(d)  * 128 + d],  s1 = sn[sec3(d)  * 128 + d];
        float c2 = cs[sec3(d2) * 128 + d2], s2 = sn[sec3(d2) * 128 + d2];

        const float* base = row + ((hh < N_HEADS) ? hh * HEAD_D
                                                  : C_EMB + (hh - N_HEADS) * HEAD_D);
        float x1 = base[d], x2 = base[d2];
        float r1 = x1 * c1 - x2 * s1;
        float r2 = x2 * c2 + x1 * s2;

        if (hh < N_HEADS) {
            g_qh[(size_t)t * C_EMB + hh * HEAD_D + d]  = __float2half(r1);
            g_qh[(size_t)t * C_EMB + hh * HEAD_D + d2] = __float2half(r2);
        } else {
            int h = hh - N_HEADS;
            size_t o = (size_t)h * T_SEQ * HEAD_D + (size_t)t * HEAD_D;
            out_k[o + d]  = r1;
            out_k[o + d2] = r2;
            g_kh[o + d]   = __float2half(r1);
            g_kh[o + d2]  = __float2half(r2);
        }
    }

#pragma unroll
    for (int it = 0; it < 2; it++) {
        int idx = it * 256 + tid;
        int h = idx >> 7, d = idx & 127;
        float v = row[C_EMB + KV_W + idx];
        size_t o = (size_t)h * T_SEQ * HEAD_D + (size_t)t * HEAD_D + d;
        out_v[o] = v;
        g_vh[o]  = __float2half(v);
    }
}

// =====================================================================
// fp16 mma flash attention (validated R9)
// =====================================================================
#define AROWB   272
#define AQ_SZ   (128 * AROWB)
#define AKV_SZ  (32 * AROWB)
#define ATSMEM  (AQ_SZ + 4 * AKV_SZ)

__global__ __launch_bounds__(256, 2)
void attn_mma(__half* __restrict__ Y)
{
    extern __shared__ char sm[];
    const uint32_t qs  = smem_u32(sm);
    const uint32_t ks0 = qs + AQ_SZ;
    const uint32_t vs0 = ks0 + 2 * AKV_SZ;

    const int h    = blockIdx.y;
    const int kvh  = h >> 2;
    const int q0   = blockIdx.x * 128;
    const int tid  = threadIdx.x;
    const int warp = tid >> 5;
    const int lane = tid & 31;
    const int g    = lane >> 2;
    const int tg   = lane & 3;
    const int lr8  = lane & 7;
    const int rsel = (lane >> 3) & 1;
    const int ksel = (lane >> 4) & 1;
    const float scale = 0.08838834764831845f;

    const __half* Ksrc = g_kh + (size_t)kvh * T_SEQ * HEAD_D;
    const __half* Vsrc = g_vh + (size_t)kvh * T_SEQ * HEAD_D;

    {
        const __half* Qsrc = g_qh + (size_t)q0 * C_EMB + h * HEAD_D;
        for (int i = tid; i < 128 * 16; i += 256) {
            int row = i >> 4, c = i & 15;
            cp_async16(qs + (uint32_t)(row * AROWB + c * 16),
                       Qsrc + (size_t)row * C_EMB + c * 8);
        }
        cp_commit();
    }

    const int ntiles = q0 / 32 + 4;

    for (int i = tid; i < 32 * 16; i += 256) {
        int row = i >> 4, c = i & 15;
        cp_async16(ks0 + (uint32_t)(row * AROWB + c * 16),
                   Ksrc + (size_t)row * HEAD_D + c * 8);
        cp_async16(vs0 + (uint32_t)(row * AROWB + c * 16),
                   Vsrc + (size_t)row * HEAD_D + c * 8);
    }
    cp_commit();

    const uint32_t qa = qs + (uint32_t)((warp * 16 + lr8 + rsel * 8) * AROWB + ksel * 16);

    float O[16][4];
#pragma unroll
    for (int n = 0; n < 16; n++)
#pragma unroll
        for (int r = 0; r < 4; r++) O[n][r] = 0.f;
    float m0 = -1e30f, m1 = -1e30f, l0 = 0.f, l1 = 0.f;

    const int row0  = q0 + warp * 16 + g;
    const int wlast = q0 + warp * 16 + 15;

    for (int kt = 0; kt < ntiles; kt++) {
        if (kt + 1 < ntiles) {
            const uint32_t kb = ks0 + (uint32_t)(((kt + 1) & 1) * AKV_SZ);
            const uint32_t vb = vs0 + (uint32_t)(((kt + 1) & 1) * AKV_SZ);
            const __half* Ki = Ksrc + (size_t)(kt + 1) * 32 * HEAD_D;
            const __half* Vi = Vsrc + (size_t)(kt + 1) * 32 * HEAD_D;
            for (int i = tid; i < 32 * 16; i += 256) {
                int row = i >> 4, c = i & 15;
                cp_async16(kb + (uint32_t)(row * AROWB + c * 16),
                           Ki + (size_t)row * HEAD_D + c * 8);
                cp_async16(vb + (uint32_t)(row * AROWB + c * 16),
                           Vi + (size_t)row * HEAD_D + c * 8);
            }
            cp_commit();
            cp_wait<1>();
        } else {
            cp_wait<0>();
        }
        __syncthreads();

        const int kk0 = kt * 32;
        const uint32_t kbuf = ks0 + (uint32_t)((kt & 1) * AKV_SZ);
        const uint32_t vbuf = vs0 + (uint32_t)((kt & 1) * AKV_SZ);

        if (kk0 <= wlast) {
            const uint32_t ka = kbuf + (uint32_t)((lr8 + ksel * 8) * AROWB + rsel * 16);

            float S[4][4];
#pragma unroll
            for (int nt = 0; nt < 4; nt++)
#pragma unroll
                for (int r = 0; r < 4; r++) S[nt][r] = 0.f;

#pragma unroll
            for (int kc = 0; kc < 8; kc++) {
                unsigned aq[4], bk2[2][4];
                ldm_x4(aq, qa + (uint32_t)(kc * 32));
                ldm_x4(bk2[0], ka + (uint32_t)(kc * 32));
                ldm_x4(bk2[1], ka + (uint32_t)(16 * AROWB + kc * 32));
#pragma unroll
                for (int nt = 0; nt < 4; nt++)
                    mma_f16(S[nt], aq, &bk2[nt >> 1][(nt & 1) * 2]);
            }

            float rm0 = -1e30f, rm1 = -1e30f;
#pragma unroll
            for (int nt = 0; nt < 4; nt++) {
                int cb = kk0 + nt * 8 + 2 * tg;
                S[nt][0] = (cb     <= row0)     ? S[nt][0] * scale : -1e30f;
                S[nt][1] = (cb + 1 <= row0)     ? S[nt][1] * scale : -1e30f;
                S[nt][2] = (cb     <= row0 + 8) ? S[nt][2] * scale : -1e30f;
                S[nt][3] = (cb + 1 <= row0 + 8) ? S[nt][3] * scale : -1e30f;
                rm0 = fmaxf(rm0, fmaxf(S[nt][0], S[nt][1]));
                rm1 = fmaxf(rm1, fmaxf(S[nt][2], S[nt][3]));
            }
            rm0 = fmaxf(rm0, __shfl_xor_sync(0xffffffffu, rm0, 1));
            rm0 = fmaxf(rm0, __shfl_xor_sync(0xffffffffu, rm0, 2));
            rm1 = fmaxf(rm1, __shfl_xor_sync(0xffffffffu, rm1, 1));
            rm1 = fmaxf(rm1, __shfl_xor_sync(0xffffffffu, rm1, 2));

            float mn0 = fmaxf(m0, rm0), mn1 = fmaxf(m1, rm1);
            float c0 = __expf(m0 - mn0), c1 = __expf(m1 - mn1);
            float s0 = 0.f, s1 = 0.f;
#pragma unroll
            for (int nt = 0; nt < 4; nt++) {
                S[nt][0] = __expf(S[nt][0] - mn0);
                S[nt][1] = __expf(S[nt][1] - mn0);
                S[nt][2] = __expf(S[nt][2] - mn1);
                S[nt][3] = __expf(S[nt][3] - mn1);
                s0 += S[nt][0] + S[nt][1];
                s1 += S[nt][2] + S[nt][3];
            }
            s0 += __shfl_xor_sync(0xffffffffu, s0, 1);
            s0 += __shfl_xor_sync(0xffffffffu, s0, 2);
            s1 += __shfl_xor_sync(0xffffffffu, s1, 1);
            s1 += __shfl_xor_sync(0xffffffffu, s1, 2);
            l0 = l0 * c0 + s0;
            l1 = l1 * c1 + s1;
            m0 = mn0; m1 = mn1;
#pragma unroll
            for (int n = 0; n < 16; n++) {
                O[n][0] *= c0; O[n][1] *= c0;
                O[n][2] *= c1; O[n][3] *= c1;
            }

#pragma unroll
            for (int kc = 0; kc < 2; kc++) {
                unsigned pa[4];
                pa[0] = pack_h2(S[2 * kc][0],     S[2 * kc][1]);
                pa[1] = pack_h2(S[2 * kc][2],     S[2 * kc][3]);
                pa[2] = pack_h2(S[2 * kc + 1][0], S[2 * kc + 1][1]);
                pa[3] = pack_h2(S[2 * kc + 1][2], S[2 * kc + 1][3]);
                const uint32_t va = vbuf +
                    (uint32_t)((kc * 16 + lr8 + rsel * 8) * AROWB + ksel * 16);
#pragma unroll
                for (int dc = 0; dc < 8; dc++) {
                    unsigned vb[4];
                    ldm_x4t(vb, va + (uint32_t)(dc * 32));
                    mma_f16(O[dc * 2],     pa, &vb[0]);
                    mma_f16(O[dc * 2 + 1], pa, &vb[2]);
                }
            }
        }
        __syncthreads();
    }

    float inv0 = 1.f / l0, inv1 = 1.f / l1;
#pragma unroll
    for (int n = 0; n < 16; n++) {
        int c = h * HEAD_D + n * 8 + 2 * tg;
        __half2 h0 = __floats2half2_rn(O[n][0] * inv0, O[n][1] * inv0);
        __half2 h1 = __floats2half2_rn(O[n][2] * inv1, O[n][3] * inv1);
        *(__half2*)&Y[(size_t)row0 * C_EMB + c]       = h0;
        *(__half2*)&Y[(size_t)(row0 + 8) * C_EMB + c] = h1;
    }
}

// =====================================================================
// launch
// =====================================================================
extern "C" void kernel_launch(void* const* d_in, const int* in_sizes, int n_in,
                              void* d_out, int out_size)
{
    (void)in_sizes; (void)n_in; (void)out_size;
    const float* x    = (const float*)d_in[0];
    const float* cosb = (const float*)d_in[1];
    const float* sinb = (const float*)d_in[2];
    const float* Wq   = (const float*)d_in[3];
    const float* bq   = (const float*)d_in[4];
    const float* Wk   = (const float*)d_in[5];
    const float* bk   = (const float*)d_in[6];
    const float* Wv   = (const float*)d_in[7];
    const float* bv   = (const float*)d_in[8];
    const float* Wo   = (const float*)d_in[9];

    float* out   = (float*)d_out;
    float* out_y = out;
    float* out_k = out + (size_t)T_SEQ * C_EMB;
    float* out_v = out_k + (size_t)N_KVH * T_SEQ * HEAD_D;

    float*  qkvb; cudaGetSymbolAddress((void**)&qkvb, g_qkv);
    __half* yhb;  cudaGetSymbolAddress((void**)&yhb,  g_yh);
    __half* xhb;  cudaGetSymbolAddress((void**)&xhb,  g_xh);
    __half* wqkv; cudaGetSymbolAddress((void**)&wqkv, g_wqkvt);
    __half* wot;  cudaGetSymbolAddress((void**)&wot,  g_wot);
    float*  bqkv; cudaGetSymbolAddress((void**)&bqkv, g_bqkv);

    cudaFuncSetAttribute(gemm_h, cudaFuncAttributeMaxDynamicSharedMemorySize, GSMEM);
    cudaFuncSetAttribute(attn_mma, cudaFuncAttributeMaxDynamicSharedMemorySize, ATSMEM);

    // 1: weight transposes
    transpose_w<<<dim3(64, 64, 4), dim3(32, 8)>>>(Wq, Wk, Wv, Wo);

    // 2: bias concat
    bias_concat<<<(QKV_W + 255) / 256, 256>>>(bq, bk, bv);

    // 3: x -> half
    convx_kernel<<<(T_SEQ * C_EMB / 4) / 256, 256>>>(x);

    // 4: fused QKV projection  <-- ncu-captured launch
    gemm_h<<<dim3(QKV_W / 256, T_SEQ / 128), 256, GSMEM>>>(xhb, wqkv, bqkv, qkvb, T_SEQ, QKV_W, C_EMB);

    // 5: RoPE + V copy
    rope2_kernel<<<T_SEQ, 256>>>(cosb, sinb, out_k, out_v);

    // 6: flash attention
    attn_mma<<<dim3(T_SEQ / 128, N_HEADS), 256, ATSMEM>>>(yhb);

    // 7: output projection
    gemm_h<<<dim3(C_EMB / 256, T_SEQ / 128), 256, GSMEM>>>(yhb, wot, nullptr, out_y, T_SEQ, C_EMB, C_EMB);
}

// round 14
// speedup vs baseline: 1.1354x; 1.1017x over previous
#include <cuda_runtime.h>
#include <cuda_fp16.h>
#include <math.h>
#include <cstdint>

// Problem constants
#define T_SEQ   2048
#define C_EMB   2048
#define N_HEADS 16
#define N_KVH   4
#define HEAD_D  128
#define KV_W    (N_KVH * HEAD_D)   // 512
#define QKV_W   (C_EMB + 2 * KV_W) // 3072

// -------- scratch (device globals; no allocation allowed) --------
__device__ float  g_qkv[T_SEQ * QKV_W];
__device__ __half g_qh[T_SEQ * C_EMB];
__device__ __half g_kh[N_KVH * T_SEQ * HEAD_D];
__device__ __half g_vh[N_KVH * T_SEQ * HEAD_D];
__device__ __half g_yh[T_SEQ * C_EMB];
__device__ __half g_xh[T_SEQ * C_EMB];
__device__ __half g_wqkvt[QKV_W * C_EMB];
__device__ __half g_wot[C_EMB * C_EMB];
__device__ float  g_bqkv[QKV_W];

// =====================================================================
// helpers
// =====================================================================
__device__ __forceinline__ uint32_t smem_u32(const void* p) {
    uint32_t a;
    asm("{ .reg .u64 t; cvta.to.shared.u64 t, %1; cvt.u32.u64 %0, t; }" : "=r"(a) : "l"(p));
    return a;
}
__device__ __forceinline__ void cp_async16(uint32_t dst, const void* src) {
    asm volatile("cp.async.ca.shared.global [%0], [%1], 16;" :: "r"(dst), "l"(src) : "memory");
}
__device__ __forceinline__ void cp_commit() {
    asm volatile("cp.async.commit_group;" ::: "memory");
}
template <int N>
__device__ __forceinline__ void cp_wait() {
    asm volatile("cp.async.wait_group %0;" :: "n"(N) : "memory");
}
__device__ __forceinline__ void ldm_x4(unsigned* r, uint32_t addr) {
    asm volatile("ldmatrix.sync.aligned.m8n8.x4.shared.b16 {%0,%1,%2,%3}, [%4];"
        : "=r"(r[0]), "=r"(r[1]), "=r"(r[2]), "=r"(r[3]) : "r"(addr));
}
__device__ __forceinline__ void ldm_x4t(unsigned* r, uint32_t addr) {
    asm volatile("ldmatrix.sync.aligned.m8n8.x4.trans.shared.b16 {%0,%1,%2,%3}, [%4];"
        : "=r"(r[0]), "=r"(r[1]), "=r"(r[2]), "=r"(r[3]) : "r"(addr));
}
__device__ __forceinline__ void mma_f16(float* c, const unsigned* a, const unsigned* b) {
    asm volatile(
        "mma.sync.aligned.m16n8k16.row.col.f32.f16.f16.f32 "
        "{%0,%1,%2,%3}, {%4,%5,%6,%7}, {%8,%9}, {%0,%1,%2,%3};"
        : "+f"(c[0]), "+f"(c[1]), "+f"(c[2]), "+f"(c[3])
        : "r"(a[0]), "r"(a[1]), "r"(a[2]), "r"(a[3]), "r"(b[0]), "r"(b[1]));
}
__device__ __forceinline__ unsigned pack_h2(float a, float b) {
    __half2 h = __floats2half2_rn(a, b);
    return *reinterpret_cast<unsigned*>(&h);
}

// =====================================================================
// fp16 mma GEMM — CTA 128(M) x 128(N), 4 warps of 64x64, 128 threads.
// 4 slots of BK=32, 2 k-tiles per sync/wait, 80KB smem -> 2 CTAs/SM:
// two independent barrier domains per SM so one CTA computes while the
// other waits (R11-R13 post-mortem: single-CTA barrier stalls the SM).
// =====================================================================
#define GROWB     80                          // 64B data + 16B pad per row
#define G_ASZ     (128 * GROWB)               // 10240
#define SLOT_SZ   (2 * G_ASZ)                 // 20480 (A + B)
#define GSMEM     (4 * SLOT_SZ)               // 81920

__global__ __launch_bounds__(128, 2)
void gemm_h(const __half* __restrict__ A, const __half* __restrict__ Bt,
            const float* __restrict__ bias, float* __restrict__ C,
            int M, int N, int K)
{
    extern __shared__ char smem[];
    const uint32_t sbase = smem_u32(smem);

    const int tid  = threadIdx.x;
    const int warp = tid >> 5;
    const int lane = tid & 31;
    const int g    = lane >> 2;
    const int tg   = lane & 3;
    const int wm   = warp >> 1;     // 0..1  (64-row band)
    const int wn   = warp & 1;      // 0..1  (64-col band)
    const int m0   = blockIdx.y * 128;
    const int n0   = blockIdx.x * 128;

    const int lr8  = lane & 7;
    const int rsel = (lane >> 3) & 1;
    const int ksel = (lane >> 4) & 1;
    const uint32_t a_base = sbase +
        (uint32_t)((wm * 64 + lr8 + rsel * 8) * GROWB + ksel * 16);
    const uint32_t b_base = sbase + G_ASZ +
        (uint32_t)((wn * 64 + lr8 + ksel * 8) * GROWB + rsel * 16);

    float acc[4][8][4];
#pragma unroll
    for (int mt = 0; mt < 4; mt++)
#pragma unroll
        for (int nt = 0; nt < 8; nt++)
#pragma unroll
            for (int r = 0; r < 4; r++) acc[mt][nt][r] = 0.f;

    const int NS = K / 64;

    // loader: per k-tile, A = 512 16B chunks (4/thread), B same
#define LOAD_TILE(kt)                                                          \
    do {                                                                       \
        const uint32_t so = (uint32_t)(((kt) & 3) * SLOT_SZ);                  \
        const __half* Ak = A + (size_t)m0 * K + (size_t)(kt) * 32;             \
        const __half* Bk = Bt + (size_t)n0 * K + (size_t)(kt) * 32;            \
        _Pragma("unroll")                                                      \
        for (int it = 0; it < 4; it++) {                                       \
            int idx = tid + it * 128;                                          \
            int row = idx >> 2, c = idx & 3;                                   \
            cp_async16(sbase + so + (uint32_t)(row * GROWB + c * 16),          \
                       Ak + (size_t)row * K + c * 8);                          \
            cp_async16(sbase + so + G_ASZ + (uint32_t)(row * GROWB + c * 16),  \
                       Bk + (size_t)row * K + c * 8);                          \
        }                                                                      \
    } while (0)

    LOAD_TILE(0);
    LOAD_TILE(1);
    cp_commit();

    for (int s = 0; s < NS; s++) {
        __syncthreads();
        if (s + 1 < NS) {
            LOAD_TILE(2 * s + 2);
            LOAD_TILE(2 * s + 3);
            cp_commit();
            cp_wait<1>();
        } else {
            cp_wait<0>();
        }
        __syncthreads();

#pragma unroll
        for (int q = 0; q < 2; q++) {
            const uint32_t soff = (uint32_t)(((2 * s + q) & 3) * SLOT_SZ);
#pragma unroll
            for (int ks = 0; ks < 2; ks++) {
                unsigned af[4][4], bf[4][4];
#pragma unroll
                for (int mt = 0; mt < 4; mt++)
                    ldm_x4(af[mt], a_base + soff + (uint32_t)(mt * 16 * GROWB + ks * 32));
#pragma unroll
                for (int pr = 0; pr < 4; pr++)
                    ldm_x4(bf[pr], b_base + soff + (uint32_t)(pr * 16 * GROWB + ks * 32));
#pragma unroll
                for (int mt = 0; mt < 4; mt++)
#pragma unroll
                    for (int nt = 0; nt < 8; nt++)
                        mma_f16(acc[mt][nt], af[mt], &bf[nt >> 1][(nt & 1) * 2]);
            }
        }
    }
#undef LOAD_TILE

    // epilogue
#pragma unroll
    for (int mt = 0; mt < 4; mt++) {
        int r0 = m0 + wm * 64 + mt * 16 + g;
#pragma unroll
        for (int nt = 0; nt < 8; nt++) {
            int c = n0 + wn * 64 + nt * 8 + 2 * tg;
            float bx = 0.f, by = 0.f;
            if (bias) { bx = bias[c]; by = bias[c + 1]; }
            float2 v0 = make_float2(acc[mt][nt][0] + bx, acc[mt][nt][1] + by);
            float2 v1 = make_float2(acc[mt][nt][2] + bx, acc[mt][nt][3] + by);
            *(float2*)&C[(size_t)r0 * N + c]       = v0;
            *(float2*)&C[(size_t)(r0 + 8) * N + c] = v1;
        }
    }
}

// =====================================================================
// x -> half
// =====================================================================
__global__ __launch_bounds__(256)
void convx_kernel(const float* __restrict__ x)
{
    int i = (blockIdx.x * 256 + threadIdx.x) * 4;
    float4 v = *(const float4*)&x[i];
    *(__half2*)&g_xh[i]     = __floats2half2_rn(v.x, v.y);
    *(__half2*)&g_xh[i + 2] = __floats2half2_rn(v.z, v.w);
}

// =====================================================================
// weight transposes and bias concat
// =====================================================================
__global__ __launch_bounds__(256)
void transpose_w(const float* __restrict__ Wq, const float* __restrict__ Wk,
                 const float* __restrict__ Wv, const float* __restrict__ Wo)
{
    __shared__ float tile[32][33];
    const int z = blockIdx.z;
    const float* in;
    __half* out;
    int C;
    if (z == 0)      { in = Wq; out = g_wqkvt;               C = C_EMB; }
    else if (z == 1) { in = Wk; out = g_wqkvt + 2048 * 2048; C = KV_W; }
    else if (z == 2) { in = Wv; out = g_wqkvt + 2560 * 2048; C = KV_W; }
    else             { in = Wo; out = g_wot;                 C = C_EMB; }
    const int bx = blockIdx.x * 32;
    if (bx >= C) return;
    const int by = blockIdx.y * 32;
    const int R = C_EMB;
    const int x = bx + threadIdx.x;
#pragma unroll
    for (int i = threadIdx.y; i < 32; i += 8)
        tile[i][threadIdx.x] = in[(size_t)(by + i) * C + x];
    __syncthreads();
    const int ox = by + threadIdx.x;
#pragma unroll
    for (int i = threadIdx.y; i < 32; i += 8)
        out[(size_t)(bx + i) * R + ox] = __float2half(tile[threadIdx.x][i]);
}

__global__ __launch_bounds__(256)
void bias_concat(const float* __restrict__ bq, const float* __restrict__ bk,
                 const float* __restrict__ bv)
{
    int idx = blockIdx.x * 256 + threadIdx.x;
    if (idx >= QKV_W) return;
    float v = (idx < 2048) ? bq[idx]
            : (idx < 2560) ? bk[idx - 2048]
                           : bv[idx - 2560];
    g_bqkv[idx] = v;
}

// =====================================================================
// RoPE + V copy (validated R9)
// =====================================================================
__device__ __forceinline__ int sec3(int d) {
    if (d < 16)  return 0;
    if (d < 40)  return 1;
    if (d < 64)  return 2;
    if (d < 80)  return 0;
    if (d < 104) return 1;
    return 2;
}

__global__ __launch_bounds__(256)
void rope2_kernel(const float* __restrict__ cosb, const float* __restrict__ sinb,
                  float* __restrict__ out_k, float* __restrict__ out_v)
{
    __shared__ float cs[384], sn[384];
    const int t   = blockIdx.x;
    const int tid = threadIdx.x;

    for (int i = tid; i < 384; i += 256) {
        int ch = i >> 7, d = i & 127;
        cs[i] = cosb[(size_t)ch * T_SEQ * HEAD_D + (size_t)t * HEAD_D + d];
        sn[i] = sinb[(size_t)ch * T_SEQ * HEAD_D + (size_t)t * HEAD_D + d];
    }
    __syncthreads();

    const float* row = g_qkv + (size_t)t * QKV_W;

#pragma unroll
    for (int it = 0; it < 5; it++) {
        int p  = it * 256 + tid;
        int hh = p >> 6;
        int d  = p & 63;
        int d2 = d + 64;
        float c1 = cs[sec3(d)  * 128 + d],  s1 = sn[sec3(d)  * 128 + d];
        float c2 = cs[sec3(d2) * 128 + d2], s2 = sn[sec3(d2) * 128 + d2];

        const float* base = row + ((hh < N_HEADS) ? hh * HEAD_D
                                                  : C_EMB + (hh - N_HEADS) * HEAD_D);
        float x1 = base[d], x2 = base[d2];
        float r1 = x1 * c1 - x2 * s1;
        float r2 = x2 * c2 + x1 * s2;

        if (hh < N_HEADS) {
            g_qh[(size_t)t * C_EMB + hh * HEAD_D + d]  = __float2half(r1);
            g_qh[(size_t)t * C_EMB + hh * HEAD_D + d2] = __float2half(r2);
        } else {
            int h = hh - N_HEADS;
            size_t o = (size_t)h * T_SEQ * HEAD_D + (size_t)t * HEAD_D;
            out_k[o + d]  = r1;
            out_k[o + d2] = r2;
            g_kh[o + d]   = __float2half(r1);
            g_kh[o + d2]  = __float2half(r2);
        }
    }

#pragma unroll
    for (int it = 0; it < 2; it++) {
        int idx = it * 256 + tid;
        int h = idx >> 7, d = idx & 127;
        float v = row[C_EMB + KV_W + idx];
        size_t o = (size_t)h * T_SEQ * HEAD_D + (size_t)t * HEAD_D + d;
        out_v[o] = v;
        g_vh[o]  = __float2half(v);
    }
}

// =====================================================================
// fp16 mma flash attention (validated R9)
// =====================================================================
#define AROWB   272
#define AQ_SZ   (128 * AROWB)
#define AKV_SZ  (32 * AROWB)
#define ATSMEM  (AQ_SZ + 4 * AKV_SZ)

__global__ __launch_bounds__(256, 2)
void attn_mma(__half* __restrict__ Y)
{
    extern __shared__ char sm[];
    const uint32_t qs  = smem_u32(sm);
    const uint32_t ks0 = qs + AQ_SZ;
    const uint32_t vs0 = ks0 + 2 * AKV_SZ;

    const int h    = blockIdx.y;
    const int kvh  = h >> 2;
    const int q0   = blockIdx.x * 128;
    const int tid  = threadIdx.x;
    const int warp = tid >> 5;
    const int lane = tid & 31;
    const int g    = lane >> 2;
    const int tg   = lane & 3;
    const int lr8  = lane & 7;
    const int rsel = (lane >> 3) & 1;
    const int ksel = (lane >> 4) & 1;
    const float scale = 0.08838834764831845f;

    const __half* Ksrc = g_kh + (size_t)kvh * T_SEQ * HEAD_D;
    const __half* Vsrc = g_vh + (size_t)kvh * T_SEQ * HEAD_D;

    {
        const __half* Qsrc = g_qh + (size_t)q0 * C_EMB + h * HEAD_D;
        for (int i = tid; i < 128 * 16; i += 256) {
            int row = i >> 4, c = i & 15;
            cp_async16(qs + (uint32_t)(row * AROWB + c * 16),
                       Qsrc + (size_t)row * C_EMB + c * 8);
        }
        cp_commit();
    }

    const int ntiles = q0 / 32 + 4;

    for (int i = tid; i < 32 * 16; i += 256) {
        int row = i >> 4, c = i & 15;
        cp_async16(ks0 + (uint32_t)(row * AROWB + c * 16),
                   Ksrc + (size_t)row * HEAD_D + c * 8);
        cp_async16(vs0 + (uint32_t)(row * AROWB + c * 16),
                   Vsrc + (size_t)row * HEAD_D + c * 8);
    }
    cp_commit();

    const uint32_t qa = qs + (uint32_t)((warp * 16 + lr8 + rsel * 8) * AROWB + ksel * 16);

    float O[16][4];
#pragma unroll
    for (int n = 0; n < 16; n++)
#pragma unroll
        for (int r = 0; r < 4; r++) O[n][r] = 0.f;
    float m0 = -1e30f, m1 = -1e30f, l0 = 0.f, l1 = 0.f;

    const int row0  = q0 + warp * 16 + g;
    const int wlast = q0 + warp * 16 + 15;

    for (int kt = 0; kt < ntiles; kt++) {
        if (kt + 1 < ntiles) {
            const uint32_t kb = ks0 + (uint32_t)(((kt + 1) & 1) * AKV_SZ);
            const uint32_t vb = vs0 + (uint32_t)(((kt + 1) & 1) * AKV_SZ);
            const __half* Ki = Ksrc + (size_t)(kt + 1) * 32 * HEAD_D;
            const __half* Vi = Vsrc + (size_t)(kt + 1) * 32 * HEAD_D;
            for (int i = tid; i < 32 * 16; i += 256) {
                int row = i >> 4, c = i & 15;
                cp_async16(kb + (uint32_t)(row * AROWB + c * 16),
                           Ki + (size_t)row * HEAD_D + c * 8);
                cp_async16(vb + (uint32_t)(row * AROWB + c * 16),
                           Vi + (size_t)row * HEAD_D + c * 8);
            }
            cp_commit();
            cp_wait<1>();
        } else {
            cp_wait<0>();
        }
        __syncthreads();

        const int kk0 = kt * 32;
        const uint32_t kbuf = ks0 + (uint32_t)((kt & 1) * AKV_SZ);
        const uint32_t vbuf = vs0 + (uint32_t)((kt & 1) * AKV_SZ);

        if (kk0 <= wlast) {
            const uint32_t ka = kbuf + (uint32_t)((lr8 + ksel * 8) * AROWB + rsel * 16);

            float S[4][4];
#pragma unroll
            for (int nt = 0; nt < 4; nt++)
#pragma unroll
                for (int r = 0; r < 4; r++) S[nt][r] = 0.f;

#pragma unroll
            for (int kc = 0; kc < 8; kc++) {
                unsigned aq[4], bk2[2][4];
                ldm_x4(aq, qa + (uint32_t)(kc * 32));
                ldm_x4(bk2[0], ka + (uint32_t)(kc * 32));
                ldm_x4(bk2[1], ka + (uint32_t)(16 * AROWB + kc * 32));
#pragma unroll
                for (int nt = 0; nt < 4; nt++)
                    mma_f16(S[nt], aq, &bk2[nt >> 1][(nt & 1) * 2]);
            }

            float rm0 = -1e30f, rm1 = -1e30f;
#pragma unroll
            for (int nt = 0; nt < 4; nt++) {
                int cb = kk0 + nt * 8 + 2 * tg;
                S[nt][0] = (cb     <= row0)     ? S[nt][0] * scale : -1e30f;
                S[nt][1] = (cb + 1 <= row0)     ? S[nt][1] * scale : -1e30f;
                S[nt][2] = (cb     <= row0 + 8) ? S[nt][2] * scale : -1e30f;
                S[nt][3] = (cb + 1 <= row0 + 8) ? S[nt][3] * scale : -1e30f;
                rm0 = fmaxf(rm0, fmaxf(S[nt][0], S[nt][1]));
                rm1 = fmaxf(rm1, fmaxf(S[nt][2], S[nt][3]));
            }
            rm0 = fmaxf(rm0, __shfl_xor_sync(0xffffffffu, rm0, 1));
            rm0 = fmaxf(rm0, __shfl_xor_sync(0xffffffffu, rm0, 2));
            rm1 = fmaxf(rm1, __shfl_xor_sync(0xffffffffu, rm1, 1));
            rm1 = fmaxf(rm1, __shfl_xor_sync(0xffffffffu, rm1, 2));

            float mn0 = fmaxf(m0, rm0), mn1 = fmaxf(m1, rm1);
            float c0 = __expf(m0 - mn0), c1 = __expf(m1 - mn1);
            float s0 = 0.f, s1 = 0.f;
#pragma unroll
            for (int nt = 0; nt < 4; nt++) {
                S[nt][0] = __expf(S[nt][0] - mn0);
                S[nt][1] = __expf(S[nt][1] - mn0);
                S[nt][2] = __expf(S[nt][2] - mn1);
                S[nt][3] = __expf(S[nt][3] - mn1);
                s0 += S[nt][0] + S[nt][1];
                s1 += S[nt][2] + S[nt][3];
            }
            s0 += __shfl_xor_sync(0xffffffffu, s0, 1);
            s0 += __shfl_xor_sync(0xffffffffu, s0, 2);
            s1 += __shfl_xor_sync(0xffffffffu, s1, 1);
            s1 += __shfl_xor_sync(0xffffffffu, s1, 2);
            l0 = l0 * c0 + s0;
            l1 = l1 * c1 + s1;
            m0 = mn0; m1 = mn1;
#pragma unroll
            for (int n = 0; n < 16; n++) {
                O[n][0] *= c0; O[n][1] *= c0;
                O[n][2] *= c1; O[n][3] *= c1;
            }

#pragma unroll
            for (int kc = 0; kc < 2; kc++) {
                unsigned pa[4];
                pa[0] = pack_h2(S[2 * kc][0],     S[2 * kc][1]);
                pa[1] = pack_h2(S[2 * kc][2],     S[2 * kc][3]);
                pa[2] = pack_h2(S[2 * kc + 1][0], S[2 * kc + 1][1]);
                pa[3] = pack_h2(S[2 * kc + 1][2], S[2 * kc + 1][3]);
                const uint32_t va = vbuf +
                    (uint32_t)((kc * 16 + lr8 + rsel * 8) * AROWB + ksel * 16);
#pragma unroll
                for (int dc = 0; dc < 8; dc++) {
                    unsigned vb[4];
                    ldm_x4t(vb, va + (uint32_t)(dc * 32));
                    mma_f16(O[dc * 2],     pa, &vb[0]);
                    mma_f16(O[dc * 2 + 1], pa, &vb[2]);
                }
            }
        }
        __syncthreads();
    }

    float inv0 = 1.f / l0, inv1 = 1.f / l1;
#pragma unroll
    for (int n = 0; n < 16; n++) {
        int c = h * HEAD_D + n * 8 + 2 * tg;
        __half2 h0 = __floats2half2_rn(O[n][0] * inv0, O[n][1] * inv0);
        __half2 h1 = __floats2half2_rn(O[n][2] * inv1, O[n][3] * inv1);
        *(__half2*)&Y[(size_t)row0 * C_EMB + c]       = h0;
        *(__half2*)&Y[(size_t)(row0 + 8) * C_EMB + c] = h1;
    }
}

// =====================================================================
// launch
// =====================================================================
extern "C" void kernel_launch(void* const* d_in, const int* in_sizes, int n_in,
                              void* d_out, int out_size)
{
    (void)in_sizes; (void)n_in; (void)out_size;
    const float* x    = (const float*)d_in[0];
    const float* cosb = (const float*)d_in[1];
    const float* sinb = (const float*)d_in[2];
    const float* Wq   = (const float*)d_in[3];
    const float* bq   = (const float*)d_in[4];
    const float* Wk   = (const float*)d_in[5];
    const float* bk   = (const float*)d_in[6];
    const float* Wv   = (const float*)d_in[7];
    const float* bv   = (const float*)d_in[8];
    const float* Wo   = (const float*)d_in[9];

    float* out   = (float*)d_out;
    float* out_y = out;
    float* out_k = out + (size_t)T_SEQ * C_EMB;
    float* out_v = out_k + (size_t)N_KVH * T_SEQ * HEAD_D;

    float*  qkvb; cudaGetSymbolAddress((void**)&qkvb, g_qkv);
    __half* yhb;  cudaGetSymbolAddress((void**)&yhb,  g_yh);
    __half* xhb;  cudaGetSymbolAddress((void**)&xhb,  g_xh);
    __half* wqkv; cudaGetSymbolAddress((void**)&wqkv, g_wqkvt);
    __half* wot;  cudaGetSymbolAddress((void**)&wot,  g_wot);
    float*  bqkv; cudaGetSymbolAddress((void**)&bqkv, g_bqkv);

    cudaFuncSetAttribute(gemm_h, cudaFuncAttributeMaxDynamicSharedMemorySize, GSMEM);
    cudaFuncSetAttribute(attn_mma, cudaFuncAttributeMaxDynamicSharedMemorySize, ATSMEM);

    // 1: weight transposes
    transpose_w<<<dim3(64, 64, 4), dim3(32, 8)>>>(Wq, Wk, Wv, Wo);

    // 2: bias concat
    bias_concat<<<(QKV_W + 255) / 256, 256>>>(bq, bk, bv);

    // 3: x -> half
    convx_kernel<<<(T_SEQ * C_EMB / 4) / 256, 256>>>(x);

    // 4: fused QKV projection  <-- ncu-captured launch
    gemm_h<<<dim3(QKV_W / 128, T_SEQ / 128), 128, GSMEM>>>(xhb, wqkv, bqkv, qkvb, T_SEQ, QKV_W, C_EMB);

    // 5: RoPE + V copy
    rope2_kernel<<<T_SEQ, 256>>>(cosb, sinb, out_k, out_v);

    // 6: flash attention
    attn_mma<<<dim3(T_SEQ / 128, N_HEADS), 256, ATSMEM>>>(yhb);

    // 7: output projection
    gemm_h<<<dim3(C_EMB / 128, T_SEQ / 128), 128, GSMEM>>>(yhb, wot, nullptr, out_y, T_SEQ, C_EMB, C_EMB);
}

// round 15
// speedup vs baseline: 1.1559x; 1.0181x over previous
#include <cuda_runtime.h>
#include <cuda_fp16.h>
#include <math.h>
#include <cstdint>

// Problem constants
#define T_SEQ   2048
#define C_EMB   2048
#define N_HEADS 16
#define N_KVH   4
#define HEAD_D  128
#define KV_W    (N_KVH * HEAD_D)   // 512
#define QKV_W   (C_EMB + 2 * KV_W) // 3072

// -------- scratch (device globals; no allocation allowed) --------
__device__ float  g_qkv[T_SEQ * QKV_W];
__device__ __half g_qh[T_SEQ * C_EMB];
__device__ __half g_kh[N_KVH * T_SEQ * HEAD_D];
__device__ __half g_vh[N_KVH * T_SEQ * HEAD_D];
__device__ __half g_yh[T_SEQ * C_EMB];
__device__ __half g_xh[T_SEQ * C_EMB];
__device__ __half g_wqkvt[QKV_W * C_EMB];
__device__ __half g_wot[C_EMB * C_EMB];
__device__ float  g_bqkv[QKV_W];

// =====================================================================
// helpers
// =====================================================================
__device__ __forceinline__ uint32_t smem_u32(const void* p) {
    uint32_t a;
    asm("{ .reg .u64 t; cvta.to.shared.u64 t, %1; cvt.u32.u64 %0, t; }" : "=r"(a) : "l"(p));
    return a;
}
__device__ __forceinline__ void cp_async16(uint32_t dst, const void* src) {
    asm volatile("cp.async.ca.shared.global [%0], [%1], 16;" :: "r"(dst), "l"(src) : "memory");
}
__device__ __forceinline__ void cp_commit() {
    asm volatile("cp.async.commit_group;" ::: "memory");
}
template <int N>
__device__ __forceinline__ void cp_wait() {
    asm volatile("cp.async.wait_group %0;" :: "n"(N) : "memory");
}
__device__ __forceinline__ void ldm_x4(unsigned* r, uint32_t addr) {
    asm volatile("ldmatrix.sync.aligned.m8n8.x4.shared.b16 {%0,%1,%2,%3}, [%4];"
        : "=r"(r[0]), "=r"(r[1]), "=r"(r[2]), "=r"(r[3]) : "r"(addr));
}
__device__ __forceinline__ void ldm_x4t(unsigned* r, uint32_t addr) {
    asm volatile("ldmatrix.sync.aligned.m8n8.x4.trans.shared.b16 {%0,%1,%2,%3}, [%4];"
        : "=r"(r[0]), "=r"(r[1]), "=r"(r[2]), "=r"(r[3]) : "r"(addr));
}
__device__ __forceinline__ void mma_f16(float* c, const unsigned* a, const unsigned* b) {
    asm volatile(
        "mma.sync.aligned.m16n8k16.row.col.f32.f16.f16.f32 "
        "{%0,%1,%2,%3}, {%4,%5,%6,%7}, {%8,%9}, {%0,%1,%2,%3};"
        : "+f"(c[0]), "+f"(c[1]), "+f"(c[2]), "+f"(c[3])
        : "r"(a[0]), "r"(a[1]), "r"(a[2]), "r"(a[3]), "r"(b[0]), "r"(b[1]));
}
__device__ __forceinline__ unsigned pack_h2(float a, float b) {
    __half2 h = __floats2half2_rn(a, b);
    return *reinterpret_cast<unsigned*>(&h);
}

// =====================================================================
// fp16 mma GEMM — validated R14: CTA 128x128, 4 warps of 64x64,
// 128 threads, 4 slots BK=32, 2 k-tiles per sync, 2 CTAs/SM.
// =====================================================================
#define GROWB     80
#define G_ASZ     (128 * GROWB)               // 10240
#define SLOT_SZ   (2 * G_ASZ)                 // 20480
#define GSMEM     (4 * SLOT_SZ)               // 81920

__global__ __launch_bounds__(128, 2)
void gemm_h(const __half* __restrict__ A, const __half* __restrict__ Bt,
            const float* __restrict__ bias, float* __restrict__ C,
            int M, int N, int K)
{
    extern __shared__ char smem[];
    const uint32_t sbase = smem_u32(smem);

    const int tid  = threadIdx.x;
    const int warp = tid >> 5;
    const int lane = tid & 31;
    const int g    = lane >> 2;
    const int tg   = lane & 3;
    const int wm   = warp >> 1;
    const int wn   = warp & 1;
    const int m0   = blockIdx.y * 128;
    const int n0   = blockIdx.x * 128;

    const int lr8  = lane & 7;
    const int rsel = (lane >> 3) & 1;
    const int ksel = (lane >> 4) & 1;
    const uint32_t a_base = sbase +
        (uint32_t)((wm * 64 + lr8 + rsel * 8) * GROWB + ksel * 16);
    const uint32_t b_base = sbase + G_ASZ +
        (uint32_t)((wn * 64 + lr8 + ksel * 8) * GROWB + rsel * 16);

    float acc[4][8][4];
#pragma unroll
    for (int mt = 0; mt < 4; mt++)
#pragma unroll
        for (int nt = 0; nt < 8; nt++)
#pragma unroll
            for (int r = 0; r < 4; r++) acc[mt][nt][r] = 0.f;

    const int NS = K / 64;

#define LOAD_TILE(kt)                                                          \
    do {                                                                       \
        const uint32_t so = (uint32_t)(((kt) & 3) * SLOT_SZ);                  \
        const __half* Ak = A + (size_t)m0 * K + (size_t)(kt) * 32;             \
        const __half* Bk = Bt + (size_t)n0 * K + (size_t)(kt) * 32;            \
        _Pragma("unroll")                                                      \
        for (int it = 0; it < 4; it++) {                                       \
            int idx = tid + it * 128;                                          \
            int row = idx >> 2, c = idx & 3;                                   \
            cp_async16(sbase + so + (uint32_t)(row * GROWB + c * 16),          \
                       Ak + (size_t)row * K + c * 8);                          \
            cp_async16(sbase + so + G_ASZ + (uint32_t)(row * GROWB + c * 16),  \
                       Bk + (size_t)row * K + c * 8);                          \
        }                                                                      \
    } while (0)

    LOAD_TILE(0);
    LOAD_TILE(1);
    cp_commit();

    for (int s = 0; s < NS; s++) {
        __syncthreads();
        if (s + 1 < NS) {
            LOAD_TILE(2 * s + 2);
            LOAD_TILE(2 * s + 3);
            cp_commit();
            cp_wait<1>();
        } else {
            cp_wait<0>();
        }
        __syncthreads();

#pragma unroll
        for (int q = 0; q < 2; q++) {
            const uint32_t soff = (uint32_t)(((2 * s + q) & 3) * SLOT_SZ);
#pragma unroll
            for (int ks = 0; ks < 2; ks++) {
                unsigned af[4][4], bf[4][4];
#pragma unroll
                for (int mt = 0; mt < 4; mt++)
                    ldm_x4(af[mt], a_base + soff + (uint32_t)(mt * 16 * GROWB + ks * 32));
#pragma unroll
                for (int pr = 0; pr < 4; pr++)
                    ldm_x4(bf[pr], b_base + soff + (uint32_t)(pr * 16 * GROWB + ks * 32));
#pragma unroll
                for (int mt = 0; mt < 4; mt++)
#pragma unroll
                    for (int nt = 0; nt < 8; nt++)
                        mma_f16(acc[mt][nt], af[mt], &bf[nt >> 1][(nt & 1) * 2]);
            }
        }
    }
#undef LOAD_TILE

#pragma unroll
    for (int mt = 0; mt < 4; mt++) {
        int r0 = m0 + wm * 64 + mt * 16 + g;
#pragma unroll
        for (int nt = 0; nt < 8; nt++) {
            int c = n0 + wn * 64 + nt * 8 + 2 * tg;
            float bx = 0.f, by = 0.f;
            if (bias) { bx = bias[c]; by = bias[c + 1]; }
            float2 v0 = make_float2(acc[mt][nt][0] + bx, acc[mt][nt][1] + by);
            float2 v1 = make_float2(acc[mt][nt][2] + bx, acc[mt][nt][3] + by);
            *(float2*)&C[(size_t)r0 * N + c]       = v0;
            *(float2*)&C[(size_t)(r0 + 8) * N + c] = v1;
        }
    }
}

// =====================================================================
// fused prep: z=0..3 weight transposes, z=4 convx + bias concat
// grid (64, 64, 5), block (32, 8)
// =====================================================================
__global__ __launch_bounds__(256)
void prep_kernel(const float* __restrict__ Wq, const float* __restrict__ Wk,
                 const float* __restrict__ Wv, const float* __restrict__ Wo,
                 const float* __restrict__ bq, const float* __restrict__ bk,
                 const float* __restrict__ bv, const float* __restrict__ x)
{
    const int z = blockIdx.z;
    const int tid = threadIdx.y * 32 + threadIdx.x;

    if (z == 4) {
        const int bid = blockIdx.y * 64 + blockIdx.x;   // 0..4095
        // convx: 4096 blocks x 256 threads x 4 floats = 4M
        int i = (bid * 256 + tid) * 4;
        float4 v = *(const float4*)&x[i];
        *(__half2*)&g_xh[i]     = __floats2half2_rn(v.x, v.y);
        *(__half2*)&g_xh[i + 2] = __floats2half2_rn(v.z, v.w);
        // bias concat in the first 12 blocks
        if (bid < 12) {
            int idx = bid * 256 + tid;
            float b = (idx < 2048) ? bq[idx]
                    : (idx < 2560) ? bk[idx - 2048]
                                   : bv[idx - 2560];
            g_bqkv[idx] = b;
        }
        return;
    }

    __shared__ float tile[32][33];
    const float* in;
    __half* out;
    int C;
    if (z == 0)      { in = Wq; out = g_wqkvt;               C = C_EMB; }
    else if (z == 1) { in = Wk; out = g_wqkvt + 2048 * 2048; C = KV_W; }
    else if (z == 2) { in = Wv; out = g_wqkvt + 2560 * 2048; C = KV_W; }
    else             { in = Wo; out = g_wot;                 C = C_EMB; }
    const int bx = blockIdx.x * 32;
    if (bx >= C) return;
    const int by = blockIdx.y * 32;
    const int R = C_EMB;
    const int xx = bx + threadIdx.x;
#pragma unroll
    for (int i = threadIdx.y; i < 32; i += 8)
        tile[i][threadIdx.x] = in[(size_t)(by + i) * C + xx];
    __syncthreads();
    const int ox = by + threadIdx.x;
#pragma unroll
    for (int i = threadIdx.y; i < 32; i += 8)
        out[(size_t)(bx + i) * R + ox] = __float2half(tile[threadIdx.x][i]);
}

// =====================================================================
// RoPE + V copy (validated R9)
// =====================================================================
__device__ __forceinline__ int sec3(int d) {
    if (d < 16)  return 0;
    if (d < 40)  return 1;
    if (d < 64)  return 2;
    if (d < 80)  return 0;
    if (d < 104) return 1;
    return 2;
}

__global__ __launch_bounds__(256)
void rope2_kernel(const float* __restrict__ cosb, const float* __restrict__ sinb,
                  float* __restrict__ out_k, float* __restrict__ out_v)
{
    __shared__ float cs[384], sn[384];
    const int t   = blockIdx.x;
    const int tid = threadIdx.x;

    for (int i = tid; i < 384; i += 256) {
        int ch = i >> 7, d = i & 127;
        cs[i] = cosb[(size_t)ch * T_SEQ * HEAD_D + (size_t)t * HEAD_D + d];
        sn[i] = sinb[(size_t)ch * T_SEQ * HEAD_D + (size_t)t * HEAD_D + d];
    }
    __syncthreads();

    const float* row = g_qkv + (size_t)t * QKV_W;

#pragma unroll
    for (int it = 0; it < 5; it++) {
        int p  = it * 256 + tid;
        int hh = p >> 6;
        int d  = p & 63;
        int d2 = d + 64;
        float c1 = cs[sec3(d)  * 128 + d],  s1 = sn[sec3(d)  * 128 + d];
        float c2 = cs[sec3(d2) * 128 + d2], s2 = sn[sec3(d2) * 128 + d2];

        const float* base = row + ((hh < N_HEADS) ? hh * HEAD_D
                                                  : C_EMB + (hh - N_HEADS) * HEAD_D);
        float x1 = base[d], x2 = base[d2];
        float r1 = x1 * c1 - x2 * s1;
        float r2 = x2 * c2 + x1 * s2;

        if (hh < N_HEADS) {
            g_qh[(size_t)t * C_EMB + hh * HEAD_D + d]  = __float2half(r1);
            g_qh[(size_t)t * C_EMB + hh * HEAD_D + d2] = __float2half(r2);
        } else {
            int h = hh - N_HEADS;
            size_t o = (size_t)h * T_SEQ * HEAD_D + (size_t)t * HEAD_D;
            out_k[o + d]  = r1;
            out_k[o + d2] = r2;
            g_kh[o + d]   = __float2half(r1);
            g_kh[o + d2]  = __float2half(r2);
        }
    }

#pragma unroll
    for (int it = 0; it < 2; it++) {
        int idx = it * 256 + tid;
        int h = idx >> 7, d = idx & 127;
        float v = row[C_EMB + KV_W + idx];
        size_t o = (size_t)h * T_SEQ * HEAD_D + (size_t)t * HEAD_D + d;
        out_v[o] = v;
        g_vh[o]  = __float2half(v);
    }
}

// =====================================================================
// fp16 mma flash attention — 64-key cp.async tiles, two 32-key softmax
// steps per tile (halves barrier/wait count vs R9; same reg pressure).
// =====================================================================
#define AROWB    272
#define AQ_SZ    (128 * AROWB)                // 34816
#define AKV64_SZ (64 * AROWB)                 // 17408
#define ATSMEM   (AQ_SZ + 4 * AKV64_SZ)       // 104448

__global__ __launch_bounds__(256, 2)
void attn_mma(__half* __restrict__ Y)
{
    extern __shared__ char sm[];
    const uint32_t qs  = smem_u32(sm);
    const uint32_t ks0 = qs + AQ_SZ;              // K bufs: ks0, ks0+AKV64_SZ
    const uint32_t vs0 = ks0 + 2 * AKV64_SZ;      // V bufs

    const int h    = blockIdx.y;
    const int kvh  = h >> 2;
    const int q0   = blockIdx.x * 128;
    const int tid  = threadIdx.x;
    const int warp = tid >> 5;
    const int lane = tid & 31;
    const int g    = lane >> 2;
    const int tg   = lane & 3;
    const int lr8  = lane & 7;
    const int rsel = (lane >> 3) & 1;
    const int ksel = (lane >> 4) & 1;
    const float scale = 0.08838834764831845f;

    const __half* Ksrc = g_kh + (size_t)kvh * T_SEQ * HEAD_D;
    const __half* Vsrc = g_vh + (size_t)kvh * T_SEQ * HEAD_D;

    // Q tile
    {
        const __half* Qsrc = g_qh + (size_t)q0 * C_EMB + h * HEAD_D;
        for (int i = tid; i < 128 * 16; i += 256) {
            int row = i >> 4, c = i & 15;
            cp_async16(qs + (uint32_t)(row * AROWB + c * 16),
                       Qsrc + (size_t)row * C_EMB + c * 8);
        }
        cp_commit();
    }

    const int nt64 = q0 / 64 + 2;   // 64-key tiles covering [0, q0+128)

    // preload tile 0
    for (int i = tid; i < 64 * 16; i += 256) {
        int row = i >> 4, c = i & 15;
        cp_async16(ks0 + (uint32_t)(row * AROWB + c * 16),
                   Ksrc + (size_t)row * HEAD_D + c * 8);
        cp_async16(vs0 + (uint32_t)(row * AROWB + c * 16),
                   Vsrc + (size_t)row * HEAD_D + c * 8);
    }
    cp_commit();

    const uint32_t qa = qs + (uint32_t)((warp * 16 + lr8 + rsel * 8) * AROWB + ksel * 16);

    float O[16][4];
#pragma unroll
    for (int n = 0; n < 16; n++)
#pragma unroll
        for (int r = 0; r < 4; r++) O[n][r] = 0.f;
    float m0 = -1e30f, m1 = -1e30f, l0 = 0.f, l1 = 0.f;

    const int row0  = q0 + warp * 16 + g;
    const int wlast = q0 + warp * 16 + 15;

    for (int kt = 0; kt < nt64; kt++) {
        if (kt + 1 < nt64) {
            const uint32_t kb = ks0 + (uint32_t)(((kt + 1) & 1) * AKV64_SZ);
            const uint32_t vb = vs0 + (uint32_t)(((kt + 1) & 1) * AKV64_SZ);
            const __half* Ki = Ksrc + (size_t)(kt + 1) * 64 * HEAD_D;
            const __half* Vi = Vsrc + (size_t)(kt + 1) * 64 * HEAD_D;
            for (int i = tid; i < 64 * 16; i += 256) {
                int row = i >> 4, c = i & 15;
                cp_async16(kb + (uint32_t)(row * AROWB + c * 16),
                           Ki + (size_t)row * HEAD_D + c * 8);
                cp_async16(vb + (uint32_t)(row * AROWB + c * 16),
                           Vi + (size_t)row * HEAD_D + c * 8);
            }
            cp_commit();
            cp_wait<1>();
        } else {
            cp_wait<0>();
        }
        __syncthreads();

        const uint32_t kbuf = ks0 + (uint32_t)((kt & 1) * AKV64_SZ);
        const uint32_t vbuf = vs0 + (uint32_t)((kt & 1) * AKV64_SZ);

        // two 32-key softmax steps within the 64-key tile
#pragma unroll
        for (int half = 0; half < 2; half++) {
            const int kk0 = kt * 64 + half * 32;
            if (kk0 > wlast) continue;

            const uint32_t ka = kbuf +
                (uint32_t)((half * 32 + lr8 + ksel * 8) * AROWB + rsel * 16);

            float S[4][4];
#pragma unroll
            for (int nt = 0; nt < 4; nt++)
#pragma unroll
                for (int r = 0; r < 4; r++) S[nt][r] = 0.f;

#pragma unroll
            for (int kc = 0; kc < 8; kc++) {
                unsigned aq[4], bk2[2][4];
                ldm_x4(aq, qa + (uint32_t)(kc * 32));
                ldm_x4(bk2[0], ka + (uint32_t)(kc * 32));
                ldm_x4(bk2[1], ka + (uint32_t)(16 * AROWB + kc * 32));
#pragma unroll
                for (int nt = 0; nt < 4; nt++)
                    mma_f16(S[nt], aq, &bk2[nt >> 1][(nt & 1) * 2]);
            }

            float rm0 = -1e30f, rm1 = -1e30f;
#pragma unroll
            for (int nt = 0; nt < 4; nt++) {
                int cb = kk0 + nt * 8 + 2 * tg;
                S[nt][0] = (cb     <= row0)     ? S[nt][0] * scale : -1e30f;
                S[nt][1] = (cb + 1 <= row0)     ? S[nt][1] * scale : -1e30f;
                S[nt][2] = (cb     <= row0 + 8) ? S[nt][2] * scale : -1e30f;
                S[nt][3] = (cb + 1 <= row0 + 8) ? S[nt][3] * scale : -1e30f;
                rm0 = fmaxf(rm0, fmaxf(S[nt][0], S[nt][1]));
                rm1 = fmaxf(rm1, fmaxf(S[nt][2], S[nt][3]));
            }
            rm0 = fmaxf(rm0, __shfl_xor_sync(0xffffffffu, rm0, 1));
            rm0 = fmaxf(rm0, __shfl_xor_sync(0xffffffffu, rm0, 2));
            rm1 = fmaxf(rm1, __shfl_xor_sync(0xffffffffu, rm1, 1));
            rm1 = fmaxf(rm1, __shfl_xor_sync(0xffffffffu, rm1, 2));

            float mn0 = fmaxf(m0, rm0), mn1 = fmaxf(m1, rm1);
            float c0 = __expf(m0 - mn0), c1 = __expf(m1 - mn1);
            float s0 = 0.f, s1 = 0.f;
#pragma unroll
            for (int nt = 0; nt < 4; nt++) {
                S[nt][0] = __expf(S[nt][0] - mn0);
                S[nt][1] = __expf(S[nt][1] - mn0);
                S[nt][2] = __expf(S[nt][2] - mn1);
                S[nt][3] = __expf(S[nt][3] - mn1);
                s0 += S[nt][0] + S[nt][1];
                s1 += S[nt][2] + S[nt][3];
            }
            s0 += __shfl_xor_sync(0xffffffffu, s0, 1);
            s0 += __shfl_xor_sync(0xffffffffu, s0, 2);
            s1 += __shfl_xor_sync(0xffffffffu, s1, 1);
            s1 += __shfl_xor_sync(0xffffffffu, s1, 2);
            l0 = l0 * c0 + s0;
            l1 = l1 * c1 + s1;
            m0 = mn0; m1 = mn1;
#pragma unroll
            for (int n = 0; n < 16; n++) {
                O[n][0] *= c0; O[n][1] *= c0;
                O[n][2] *= c1; O[n][3] *= c1;
            }

#pragma unroll
            for (int kc = 0; kc < 2; kc++) {
                unsigned pa[4];
                pa[0] = pack_h2(S[2 * kc][0],     S[2 * kc][1]);
                pa[1] = pack_h2(S[2 * kc][2],     S[2 * kc][3]);
                pa[2] = pack_h2(S[2 * kc + 1][0], S[2 * kc + 1][1]);
                pa[3] = pack_h2(S[2 * kc + 1][2], S[2 * kc + 1][3]);
                const uint32_t va = vbuf +
                    (uint32_t)((half * 32 + kc * 16 + lr8 + rsel * 8) * AROWB + ksel * 16);
#pragma unroll
                for (int dc = 0; dc < 8; dc++) {
                    unsigned vb[4];
                    ldm_x4t(vb, va + (uint32_t)(dc * 32));
                    mma_f16(O[dc * 2],     pa, &vb[0]);
                    mma_f16(O[dc * 2 + 1], pa, &vb[2]);
                }
            }
        }
        __syncthreads();
    }

    float inv0 = 1.f / l0, inv1 = 1.f / l1;
#pragma unroll
    for (int n = 0; n < 16; n++) {
        int c = h * HEAD_D + n * 8 + 2 * tg;
        __half2 h0 = __floats2half2_rn(O[n][0] * inv0, O[n][1] * inv0);
        __half2 h1 = __floats2half2_rn(O[n][2] * inv1, O[n][3] * inv1);
        *(__half2*)&Y[(size_t)row0 * C_EMB + c]       = h0;
        *(__half2*)&Y[(size_t)(row0 + 8) * C_EMB + c] = h1;
    }
}

// =====================================================================
// launch
// =====================================================================
extern "C" void kernel_launch(void* const* d_in, const int* in_sizes, int n_in,
                              void* d_out, int out_size)
{
    (void)in_sizes; (void)n_in; (void)out_size;
    const float* x    = (const float*)d_in[0];
    const float* cosb = (const float*)d_in[1];
    const float* sinb = (const float*)d_in[2];
    const float* Wq   = (const float*)d_in[3];
    const float* bq   = (const float*)d_in[4];
    const float* Wk   = (const float*)d_in[5];
    const float* bk   = (const float*)d_in[6];
    const float* Wv   = (const float*)d_in[7];
    const float* bv   = (const float*)d_in[8];
    const float* Wo   = (const float*)d_in[9];

    float* out   = (float*)d_out;
    float* out_y = out;
    float* out_k = out + (size_t)T_SEQ * C_EMB;
    float* out_v = out_k + (size_t)N_KVH * T_SEQ * HEAD_D;

    float*  qkvb; cudaGetSymbolAddress((void**)&qkvb, g_qkv);
    __half* yhb;  cudaGetSymbolAddress((void**)&yhb,  g_yh);
    __half* xhb;  cudaGetSymbolAddress((void**)&xhb,  g_xh);
    __half* wqkv; cudaGetSymbolAddress((void**)&wqkv, g_wqkvt);
    __half* wot;  cudaGetSymbolAddress((void**)&wot,  g_wot);
    float*  bqkv; cudaGetSymbolAddress((void**)&bqkv, g_bqkv);

    cudaFuncSetAttribute(gemm_h, cudaFuncAttributeMaxDynamicSharedMemorySize, GSMEM);
    cudaFuncSetAttribute(attn_mma, cudaFuncAttributeMaxDynamicSharedMemorySize, ATSMEM);

    // 1: fused prep (weight transposes + bias concat + x->half)
    prep_kernel<<<dim3(64, 64, 5), dim3(32, 8)>>>(Wq, Wk, Wv, Wo, bq, bk, bv, x);

    // 2: fused QKV projection
    gemm_h<<<dim3(QKV_W / 128, T_SEQ / 128), 128, GSMEM>>>(xhb, wqkv, bqkv, qkvb, T_SEQ, QKV_W, C_EMB);

    // 3: RoPE + V copy
    rope2_kernel<<<T_SEQ, 256>>>(cosb, sinb, out_k, out_v);

    // 4: flash attention  <-- ncu-captured launch
    attn_mma<<<dim3(T_SEQ / 128, N_HEADS), 256, ATSMEM>>>(yhb);

    // 5: output projection
    gemm_h<<<dim3(C_EMB / 128, T_SEQ / 128), 128, GSMEM>>>(yhb, wot, nullptr, out_y, T_SEQ, C_EMB, C_EMB);
}

// round 16
// speedup vs baseline: 1.1917x; 1.0309x over previous
#include <cuda_runtime.h>
#include <cuda_fp16.h>
#include <math.h>
#include <cstdint>

// Problem constants
#define T_SEQ   2048
#define C_EMB   2048
#define N_HEADS 16
#define N_KVH   4
#define HEAD_D  128
#define KV_W    (N_KVH * HEAD_D)   // 512
#define QKV_W   (C_EMB + 2 * KV_W) // 3072

// -------- scratch (device globals; no allocation allowed) --------
__device__ float  g_qkv[T_SEQ * QKV_W];
__device__ __half g_qh[T_SEQ * C_EMB];          // roped Q * 1/sqrt(d), half
__device__ __half g_kh[N_KVH * T_SEQ * HEAD_D];
__device__ __half g_vh[N_KVH * T_SEQ * HEAD_D];
__device__ __half g_yh[T_SEQ * C_EMB];
__device__ __half g_xh[T_SEQ * C_EMB];
__device__ __half g_wqkvt[QKV_W * C_EMB];
__device__ __half g_wot[C_EMB * C_EMB];
__device__ float  g_bqkv[QKV_W];

// =====================================================================
// helpers
// =====================================================================
__device__ __forceinline__ uint32_t smem_u32(const void* p) {
    uint32_t a;
    asm("{ .reg .u64 t; cvta.to.shared.u64 t, %1; cvt.u32.u64 %0, t; }" : "=r"(a) : "l"(p));
    return a;
}
__device__ __forceinline__ void cp_async16(uint32_t dst, const void* src) {
    asm volatile("cp.async.ca.shared.global [%0], [%1], 16;" :: "r"(dst), "l"(src) : "memory");
}
__device__ __forceinline__ void cp_commit() {
    asm volatile("cp.async.commit_group;" ::: "memory");
}
template <int N>
__device__ __forceinline__ void cp_wait() {
    asm volatile("cp.async.wait_group %0;" :: "n"(N) : "memory");
}
__device__ __forceinline__ void ldm_x4(unsigned* r, uint32_t addr) {
    asm volatile("ldmatrix.sync.aligned.m8n8.x4.shared.b16 {%0,%1,%2,%3}, [%4];"
        : "=r"(r[0]), "=r"(r[1]), "=r"(r[2]), "=r"(r[3]) : "r"(addr));
}
__device__ __forceinline__ void ldm_x4t(unsigned* r, uint32_t addr) {
    asm volatile("ldmatrix.sync.aligned.m8n8.x4.trans.shared.b16 {%0,%1,%2,%3}, [%4];"
        : "=r"(r[0]), "=r"(r[1]), "=r"(r[2]), "=r"(r[3]) : "r"(addr));
}
__device__ __forceinline__ void mma_f16(float* c, const unsigned* a, const unsigned* b) {
    asm volatile(
        "mma.sync.aligned.m16n8k16.row.col.f32.f16.f16.f32 "
        "{%0,%1,%2,%3}, {%4,%5,%6,%7}, {%8,%9}, {%0,%1,%2,%3};"
        : "+f"(c[0]), "+f"(c[1]), "+f"(c[2]), "+f"(c[3])
        : "r"(a[0]), "r"(a[1]), "r"(a[2]), "r"(a[3]), "r"(b[0]), "r"(b[1]));
}
__device__ __forceinline__ unsigned pack_h2(float a, float b) {
    __half2 h = __floats2half2_rn(a, b);
    return *reinterpret_cast<unsigned*>(&h);
}

// =====================================================================
// fp16 mma GEMM — validated R14: CTA 128x128, 4 warps of 64x64,
// 128 threads, 4 slots BK=32, 2 k-tiles per sync, 2 CTAs/SM.
// =====================================================================
#define GROWB     80
#define G_ASZ     (128 * GROWB)               // 10240
#define SLOT_SZ   (2 * G_ASZ)                 // 20480
#define GSMEM     (4 * SLOT_SZ)               // 81920

__global__ __launch_bounds__(128, 2)
void gemm_h(const __half* __restrict__ A, const __half* __restrict__ Bt,
            const float* __restrict__ bias, float* __restrict__ C,
            int M, int N, int K)
{
    extern __shared__ char smem[];
    const uint32_t sbase = smem_u32(smem);

    const int tid  = threadIdx.x;
    const int warp = tid >> 5;
    const int lane = tid & 31;
    const int g    = lane >> 2;
    const int tg   = lane & 3;
    const int wm   = warp >> 1;
    const int wn   = warp & 1;
    const int m0   = blockIdx.y * 128;
    const int n0   = blockIdx.x * 128;

    const int lr8  = lane & 7;
    const int rsel = (lane >> 3) & 1;
    const int ksel = (lane >> 4) & 1;
    const uint32_t a_base = sbase +
        (uint32_t)((wm * 64 + lr8 + rsel * 8) * GROWB + ksel * 16);
    const uint32_t b_base = sbase + G_ASZ +
        (uint32_t)((wn * 64 + lr8 + ksel * 8) * GROWB + rsel * 16);

    float acc[4][8][4];
#pragma unroll
    for (int mt = 0; mt < 4; mt++)
#pragma unroll
        for (int nt = 0; nt < 8; nt++)
#pragma unroll
            for (int r = 0; r < 4; r++) acc[mt][nt][r] = 0.f;

    const int NS = K / 64;

#define LOAD_TILE(kt)                                                          \
    do {                                                                       \
        const uint32_t so = (uint32_t)(((kt) & 3) * SLOT_SZ);                  \
        const __half* Ak = A + (size_t)m0 * K + (size_t)(kt) * 32;             \
        const __half* Bk = Bt + (size_t)n0 * K + (size_t)(kt) * 32;            \
        _Pragma("unroll")                                                      \
        for (int it = 0; it < 4; it++) {                                       \
            int idx = tid + it * 128;                                          \
            int row = idx >> 2, c = idx & 3;                                   \
            cp_async16(sbase + so + (uint32_t)(row * GROWB + c * 16),          \
                       Ak + (size_t)row * K + c * 8);                          \
            cp_async16(sbase + so + G_ASZ + (uint32_t)(row * GROWB + c * 16),  \
                       Bk + (size_t)row * K + c * 8);                          \
        }                                                                      \
    } while (0)

    LOAD_TILE(0);
    LOAD_TILE(1);
    cp_commit();

    for (int s = 0; s < NS; s++) {
        __syncthreads();
        if (s + 1 < NS) {
            LOAD_TILE(2 * s + 2);
            LOAD_TILE(2 * s + 3);
            cp_commit();
            cp_wait<1>();
        } else {
            cp_wait<0>();
        }
        __syncthreads();

#pragma unroll
        for (int q = 0; q < 2; q++) {
            const uint32_t soff = (uint32_t)(((2 * s + q) & 3) * SLOT_SZ);
#pragma unroll
            for (int ks = 0; ks < 2; ks++) {
                unsigned af[4][4], bf[4][4];
#pragma unroll
                for (int mt = 0; mt < 4; mt++)
                    ldm_x4(af[mt], a_base + soff + (uint32_t)(mt * 16 * GROWB + ks * 32));
#pragma unroll
                for (int pr = 0; pr < 4; pr++)
                    ldm_x4(bf[pr], b_base + soff + (uint32_t)(pr * 16 * GROWB + ks * 32));
#pragma unroll
                for (int mt = 0; mt < 4; mt++)
#pragma unroll
                    for (int nt = 0; nt < 8; nt++)
                        mma_f16(acc[mt][nt], af[mt], &bf[nt >> 1][(nt & 1) * 2]);
            }
        }
    }
#undef LOAD_TILE

#pragma unroll
    for (int mt = 0; mt < 4; mt++) {
        int r0 = m0 + wm * 64 + mt * 16 + g;
#pragma unroll
        for (int nt = 0; nt < 8; nt++) {
            int c = n0 + wn * 64 + nt * 8 + 2 * tg;
            float bx = 0.f, by = 0.f;
            if (bias) { bx = bias[c]; by = bias[c + 1]; }
            float2 v0 = make_float2(acc[mt][nt][0] + bx, acc[mt][nt][1] + by);
            float2 v1 = make_float2(acc[mt][nt][2] + bx, acc[mt][nt][3] + by);
            *(float2*)&C[(size_t)r0 * N + c]       = v0;
            *(float2*)&C[(size_t)(r0 + 8) * N + c] = v1;
        }
    }
}

// =====================================================================
// fused prep: z=0..3 weight transposes, z=4 convx + bias concat
// =====================================================================
__global__ __launch_bounds__(256)
void prep_kernel(const float* __restrict__ Wq, const float* __restrict__ Wk,
                 const float* __restrict__ Wv, const float* __restrict__ Wo,
                 const float* __restrict__ bq, const float* __restrict__ bk,
                 const float* __restrict__ bv, const float* __restrict__ x)
{
    const int z = blockIdx.z;
    const int tid = threadIdx.y * 32 + threadIdx.x;

    if (z == 4) {
        const int bid = blockIdx.y * 64 + blockIdx.x;
        int i = (bid * 256 + tid) * 4;
        float4 v = *(const float4*)&x[i];
        *(__half2*)&g_xh[i]     = __floats2half2_rn(v.x, v.y);
        *(__half2*)&g_xh[i + 2] = __floats2half2_rn(v.z, v.w);
        if (bid < 12) {
            int idx = bid * 256 + tid;
            float b = (idx < 2048) ? bq[idx]
                    : (idx < 2560) ? bk[idx - 2048]
                                   : bv[idx - 2560];
            g_bqkv[idx] = b;
        }
        return;
    }

    __shared__ float tile[32][33];
    const float* in;
    __half* out;
    int C;
    if (z == 0)      { in = Wq; out = g_wqkvt;               C = C_EMB; }
    else if (z == 1) { in = Wk; out = g_wqkvt + 2048 * 2048; C = KV_W; }
    else if (z == 2) { in = Wv; out = g_wqkvt + 2560 * 2048; C = KV_W; }
    else             { in = Wo; out = g_wot;                 C = C_EMB; }
    const int bx = blockIdx.x * 32;
    if (bx >= C) return;
    const int by = blockIdx.y * 32;
    const int R = C_EMB;
    const int xx = bx + threadIdx.x;
#pragma unroll
    for (int i = threadIdx.y; i < 32; i += 8)
        tile[i][threadIdx.x] = in[(size_t)(by + i) * C + xx];
    __syncthreads();
    const int ox = by + threadIdx.x;
#pragma unroll
    for (int i = threadIdx.y; i < 32; i += 8)
        out[(size_t)(bx + i) * R + ox] = __float2half(tile[threadIdx.x][i]);
}

// =====================================================================
// RoPE + V copy. Q half output pre-scaled by 1/sqrt(d).
// =====================================================================
__device__ __forceinline__ int sec3(int d) {
    if (d < 16)  return 0;
    if (d < 40)  return 1;
    if (d < 64)  return 2;
    if (d < 80)  return 0;
    if (d < 104) return 1;
    return 2;
}

__global__ __launch_bounds__(256)
void rope2_kernel(const float* __restrict__ cosb, const float* __restrict__ sinb,
                  float* __restrict__ out_k, float* __restrict__ out_v)
{
    __shared__ float cs[384], sn[384];
    const int t   = blockIdx.x;
    const int tid = threadIdx.x;
    const float qscale = 0.08838834764831845f;   // 1/sqrt(128)

    for (int i = tid; i < 384; i += 256) {
        int ch = i >> 7, d = i & 127;
        cs[i] = cosb[(size_t)ch * T_SEQ * HEAD_D + (size_t)t * HEAD_D + d];
        sn[i] = sinb[(size_t)ch * T_SEQ * HEAD_D + (size_t)t * HEAD_D + d];
    }
    __syncthreads();

    const float* row = g_qkv + (size_t)t * QKV_W;

#pragma unroll
    for (int it = 0; it < 5; it++) {
        int p  = it * 256 + tid;
        int hh = p >> 6;
        int d  = p & 63;
        int d2 = d + 64;
        float c1 = cs[sec3(d)  * 128 + d],  s1 = sn[sec3(d)  * 128 + d];
        float c2 = cs[sec3(d2) * 128 + d2], s2 = sn[sec3(d2) * 128 + d2];

        const float* base = row + ((hh < N_HEADS) ? hh * HEAD_D
                                                  : C_EMB + (hh - N_HEADS) * HEAD_D);
        float x1 = base[d], x2 = base[d2];
        float r1 = x1 * c1 - x2 * s1;
        float r2 = x2 * c2 + x1 * s2;

        if (hh < N_HEADS) {
            g_qh[(size_t)t * C_EMB + hh * HEAD_D + d]  = __float2half(r1 * qscale);
            g_qh[(size_t)t * C_EMB + hh * HEAD_D + d2] = __float2half(r2 * qscale);
        } else {
            int h = hh - N_HEADS;
            size_t o = (size_t)h * T_SEQ * HEAD_D + (size_t)t * HEAD_D;
            out_k[o + d]  = r1;
            out_k[o + d2] = r2;
            g_kh[o + d]   = __float2half(r1);
            g_kh[o + d2]  = __float2half(r2);
        }
    }

#pragma unroll
    for (int it = 0; it < 2; it++) {
        int idx = it * 256 + tid;
        int h = idx >> 7, d = idx & 127;
        float v = row[C_EMB + KV_W + idx];
        size_t o = (size_t)h * T_SEQ * HEAD_D + (size_t)t * HEAD_D + d;
        out_v[o] = v;
        g_vh[o]  = __float2half(v);
    }
}

// =====================================================================
// fp16 mma flash attention — 64-key cp.async tiles, two 32-key steps.
// Q pre-scaled; full-tile fast path (no mask); vote-gated O-rescale;
// reversed q-tile launch order for causal tail packing.
// =====================================================================
#define AROWB    272
#define AQ_SZ    (128 * AROWB)
#define AKV64_SZ (64 * AROWB)
#define ATSMEM   (AQ_SZ + 4 * AKV64_SZ)       // 104448

__global__ __launch_bounds__(256, 2)
void attn_mma(__half* __restrict__ Y)
{
    extern __shared__ char sm[];
    const uint32_t qs  = smem_u32(sm);
    const uint32_t ks0 = qs + AQ_SZ;
    const uint32_t vs0 = ks0 + 2 * AKV64_SZ;

    const int h    = blockIdx.y;
    const int kvh  = h >> 2;
    const int q0   = (int)(gridDim.x - 1 - blockIdx.x) * 128;   // heavy blocks first
    const int tid  = threadIdx.x;
    const int warp = tid >> 5;
    const int lane = tid & 31;
    const int g    = lane >> 2;
    const int tg   = lane & 3;
    const int lr8  = lane & 7;
    const int rsel = (lane >> 3) & 1;
    const int ksel = (lane >> 4) & 1;

    const __half* Ksrc = g_kh + (size_t)kvh * T_SEQ * HEAD_D;
    const __half* Vsrc = g_vh + (size_t)kvh * T_SEQ * HEAD_D;

    // Q tile
    {
        const __half* Qsrc = g_qh + (size_t)q0 * C_EMB + h * HEAD_D;
        for (int i = tid; i < 128 * 16; i += 256) {
            int row = i >> 4, c = i & 15;
            cp_async16(qs + (uint32_t)(row * AROWB + c * 16),
                       Qsrc + (size_t)row * C_EMB + c * 8);
        }
        cp_commit();
    }

    const int nt64 = q0 / 64 + 2;

    for (int i = tid; i < 64 * 16; i += 256) {
        int row = i >> 4, c = i & 15;
        cp_async16(ks0 + (uint32_t)(row * AROWB + c * 16),
                   Ksrc + (size_t)row * HEAD_D + c * 8);
        cp_async16(vs0 + (uint32_t)(row * AROWB + c * 16),
                   Vsrc + (size_t)row * HEAD_D + c * 8);
    }
    cp_commit();

    const uint32_t qa = qs + (uint32_t)((warp * 16 + lr8 + rsel * 8) * AROWB + ksel * 16);

    float O[16][4];
#pragma unroll
    for (int n = 0; n < 16; n++)
#pragma unroll
        for (int r = 0; r < 4; r++) O[n][r] = 0.f;
    float m0 = -1e30f, m1 = -1e30f, l0 = 0.f, l1 = 0.f;

    const int row0  = q0 + warp * 16 + g;
    const int wfirst = q0 + warp * 16;      // first q row of this warp
    const int wlast  = wfirst + 15;

    for (int kt = 0; kt < nt64; kt++) {
        if (kt + 1 < nt64) {
            const uint32_t kb = ks0 + (uint32_t)(((kt + 1) & 1) * AKV64_SZ);
            const uint32_t vb = vs0 + (uint32_t)(((kt + 1) & 1) * AKV64_SZ);
            const __half* Ki = Ksrc + (size_t)(kt + 1) * 64 * HEAD_D;
            const __half* Vi = Vsrc + (size_t)(kt + 1) * 64 * HEAD_D;
            for (int i = tid; i < 64 * 16; i += 256) {
                int row = i >> 4, c = i & 15;
                cp_async16(kb + (uint32_t)(row * AROWB + c * 16),
                           Ki + (size_t)row * HEAD_D + c * 8);
                cp_async16(vb + (uint32_t)(row * AROWB + c * 16),
                           Vi + (size_t)row * HEAD_D + c * 8);
            }
            cp_commit();
            cp_wait<1>();
        } else {
            cp_wait<0>();
        }
        __syncthreads();

        const uint32_t kbuf = ks0 + (uint32_t)((kt & 1) * AKV64_SZ);
        const uint32_t vbuf = vs0 + (uint32_t)((kt & 1) * AKV64_SZ);

#pragma unroll
        for (int half = 0; half < 2; half++) {
            const int kk0 = kt * 64 + half * 32;
            if (kk0 > wlast) continue;

            const uint32_t ka = kbuf +
                (uint32_t)((half * 32 + lr8 + ksel * 8) * AROWB + rsel * 16);

            float S[4][4];
#pragma unroll
            for (int nt = 0; nt < 4; nt++)
#pragma unroll
                for (int r = 0; r < 4; r++) S[nt][r] = 0.f;

#pragma unroll
            for (int kc = 0; kc < 8; kc++) {
                unsigned aq[4], bk2[2][4];
                ldm_x4(aq, qa + (uint32_t)(kc * 32));
                ldm_x4(bk2[0], ka + (uint32_t)(kc * 32));
                ldm_x4(bk2[1], ka + (uint32_t)(16 * AROWB + kc * 32));
#pragma unroll
                for (int nt = 0; nt < 4; nt++)
                    mma_f16(S[nt], aq, &bk2[nt >> 1][(nt & 1) * 2]);
            }

            // masking: only diagonal steps need it (warp-uniform condition)
            if (kk0 + 31 >= wfirst) {
#pragma unroll
                for (int nt = 0; nt < 4; nt++) {
                    int cb = kk0 + nt * 8 + 2 * tg;
                    S[nt][0] = (cb     <= row0)     ? S[nt][0] : -1e30f;
                    S[nt][1] = (cb + 1 <= row0)     ? S[nt][1] : -1e30f;
                    S[nt][2] = (cb     <= row0 + 8) ? S[nt][2] : -1e30f;
                    S[nt][3] = (cb + 1 <= row0 + 8) ? S[nt][3] : -1e30f;
                }
            }

            float rm0 = -1e30f, rm1 = -1e30f;
#pragma unroll
            for (int nt = 0; nt < 4; nt++) {
                rm0 = fmaxf(rm0, fmaxf(S[nt][0], S[nt][1]));
                rm1 = fmaxf(rm1, fmaxf(S[nt][2], S[nt][3]));
            }
            rm0 = fmaxf(rm0, __shfl_xor_sync(0xffffffffu, rm0, 1));
            rm0 = fmaxf(rm0, __shfl_xor_sync(0xffffffffu, rm0, 2));
            rm1 = fmaxf(rm1, __shfl_xor_sync(0xffffffffu, rm1, 1));
            rm1 = fmaxf(rm1, __shfl_xor_sync(0xffffffffu, rm1, 2));

            float mn0 = fmaxf(m0, rm0), mn1 = fmaxf(m1, rm1);

            // vote-gated rescale: skip O-rescale when no lane's max moved
            unsigned upd = __ballot_sync(0xffffffffu, (mn0 > m0) || (mn1 > m1));
            if (upd) {
                float c0 = __expf(m0 - mn0), c1 = __expf(m1 - mn1);
                l0 *= c0; l1 *= c1;
#pragma unroll
                for (int n = 0; n < 16; n++) {
                    O[n][0] *= c0; O[n][1] *= c0;
                    O[n][2] *= c1; O[n][3] *= c1;
                }
                m0 = mn0; m1 = mn1;
            }

            float s0 = 0.f, s1 = 0.f;
#pragma unroll
            for (int nt = 0; nt < 4; nt++) {
                S[nt][0] = __expf(S[nt][0] - m0);
                S[nt][1] = __expf(S[nt][1] - m0);
                S[nt][2] = __expf(S[nt][2] - m1);
                S[nt][3] = __expf(S[nt][3] - m1);
                s0 += S[nt][0] + S[nt][1];
                s1 += S[nt][2] + S[nt][3];
            }
            s0 += __shfl_xor_sync(0xffffffffu, s0, 1);
            s0 += __shfl_xor_sync(0xffffffffu, s0, 2);
            s1 += __shfl_xor_sync(0xffffffffu, s1, 1);
            s1 += __shfl_xor_sync(0xffffffffu, s1, 2);
            l0 += s0;
            l1 += s1;

#pragma unroll
            for (int kc = 0; kc < 2; kc++) {
                unsigned pa[4];
                pa[0] = pack_h2(S[2 * kc][0],     S[2 * kc][1]);
                pa[1] = pack_h2(S[2 * kc][2],     S[2 * kc][3]);
                pa[2] = pack_h2(S[2 * kc + 1][0], S[2 * kc + 1][1]);
                pa[3] = pack_h2(S[2 * kc + 1][2], S[2 * kc + 1][3]);
                const uint32_t va = vbuf +
                    (uint32_t)((half * 32 + kc * 16 + lr8 + rsel * 8) * AROWB + ksel * 16);
#pragma unroll
                for (int dc = 0; dc < 8; dc++) {
                    unsigned vb[4];
                    ldm_x4t(vb, va + (uint32_t)(dc * 32));
                    mma_f16(O[dc * 2],     pa, &vb[0]);
                    mma_f16(O[dc * 2 + 1], pa, &vb[2]);
                }
            }
        }
        __syncthreads();
    }

    float inv0 = 1.f / l0, inv1 = 1.f / l1;
#pragma unroll
    for (int n = 0; n < 16; n++) {
        int c = h * HEAD_D + n * 8 + 2 * tg;
        __half2 h0 = __floats2half2_rn(O[n][0] * inv0, O[n][1] * inv0);
        __half2 h1 = __floats2half2_rn(O[n][2] * inv1, O[n][3] * inv1);
        *(__half2*)&Y[(size_t)row0 * C_EMB + c]       = h0;
        *(__half2*)&Y[(size_t)(row0 + 8) * C_EMB + c] = h1;
    }
}

// =====================================================================
// launch
// =====================================================================
extern "C" void kernel_launch(void* const* d_in, const int* in_sizes, int n_in,
                              void* d_out, int out_size)
{
    (void)in_sizes; (void)n_in; (void)out_size;
    const float* x    = (const float*)d_in[0];
    const float* cosb = (const float*)d_in[1];
    const float* sinb = (const float*)d_in[2];
    const float* Wq   = (const float*)d_in[3];
    const float* bq   = (const float*)d_in[4];
    const float* Wk   = (const float*)d_in[5];
    const float* bk   = (const float*)d_in[6];
    const float* Wv   = (const float*)d_in[7];
    const float* bv   = (const float*)d_in[8];
    const float* Wo   = (const float*)d_in[9];

    float* out   = (float*)d_out;
    float* out_y = out;
    float* out_k = out + (size_t)T_SEQ * C_EMB;
    float* out_v = out_k + (size_t)N_KVH * T_SEQ * HEAD_D;

    float*  qkvb; cudaGetSymbolAddress((void**)&qkvb, g_qkv);
    __half* yhb;  cudaGetSymbolAddress((void**)&yhb,  g_yh);
    __half* xhb;  cudaGetSymbolAddress((void**)&xhb,  g_xh);
    __half* wqkv; cudaGetSymbolAddress((void**)&wqkv, g_wqkvt);
    __half* wot;  cudaGetSymbolAddress((void**)&wot,  g_wot);
    float*  bqkv; cudaGetSymbolAddress((void**)&bqkv, g_bqkv);

    cudaFuncSetAttribute(gemm_h, cudaFuncAttributeMaxDynamicSharedMemorySize, GSMEM);
    cudaFuncSetAttribute(attn_mma, cudaFuncAttributeMaxDynamicSharedMemorySize, ATSMEM);

    // 1: fused prep (weight transposes + bias concat + x->half)
    prep_kernel<<<dim3(64, 64, 5), dim3(32, 8)>>>(Wq, Wk, Wv, Wo, bq, bk, bv, x);

    // 2: fused QKV projection
    gemm_h<<<dim3(QKV_W / 128, T_SEQ / 128), 128, GSMEM>>>(xhb, wqkv, bqkv, qkvb, T_SEQ, QKV_W, C_EMB);

    // 3: RoPE + V copy (Q pre-scaled)
    rope2_kernel<<<T_SEQ, 256>>>(cosb, sinb, out_k, out_v);

    // 4: flash attention  <-- ncu-captured launch
    attn_mma<<<dim3(T_SEQ / 128, N_HEADS), 256, ATSMEM>>>(yhb);

    // 5: output projection
    gemm_h<<<dim3(C_EMB / 128, T_SEQ / 128), 128, GSMEM>>>(yhb, wot, nullptr, out_y, T_SEQ, C_EMB, C_EMB);
}